// round 1
// baseline (speedup 1.0000x reference)
#include <cuda_runtime.h>

#define BATCH   16
#define CCH     512
#define NPIX    1024          // 32*32
#define HEADS   4
#define HD      128           // CCH / HEADS
#define GROUPS  32
#define CPG     (CCH / GROUPS)   // 16
#define GEPS    1e-5f

// ---------------- scratch (device globals; no allocations allowed) ----------
__device__ float g_xn [BATCH * CCH * NPIX];            //  33.5 MB
__device__ float g_qkv[BATCH * 3 * CCH * NPIX];        // 100.7 MB
__device__ float g_S  [BATCH * HEADS * NPIX * NPIX];   // 268.4 MB
__device__ float g_att[BATCH * CCH * NPIX];            //  33.5 MB

// ---------------- GroupNorm -------------------------------------------------
__global__ void gn_kernel(const float* __restrict__ x,
                          const float* __restrict__ gamma,
                          const float* __restrict__ beta) {
    const int bg = blockIdx.x;                  // b*GROUPS + g
    const int b  = bg / GROUPS;
    const int g  = bg % GROUPS;
    const int M  = CPG * NPIX;                  // 16384
    const float* xp = x + ((size_t)b * CCH + (size_t)g * CPG) * NPIX;
    float*       op = g_xn + ((size_t)b * CCH + (size_t)g * CPG) * NPIX;

    float s = 0.f, ss = 0.f;
    for (int i = threadIdx.x; i < M; i += blockDim.x) {
        float v = xp[i];
        s += v; ss += v * v;
    }
    __shared__ float red[64];
    #pragma unroll
    for (int o = 16; o; o >>= 1) {
        s  += __shfl_xor_sync(0xffffffffu, s,  o);
        ss += __shfl_xor_sync(0xffffffffu, ss, o);
    }
    const int warp = threadIdx.x >> 5, lane = threadIdx.x & 31;
    if (lane == 0) { red[warp] = s; red[warp + 32] = ss; }
    __syncthreads();
    if (threadIdx.x < 32) {
        float s2  = (threadIdx.x < 8) ? red[threadIdx.x]      : 0.f;
        float ss2 = (threadIdx.x < 8) ? red[threadIdx.x + 32] : 0.f;
        #pragma unroll
        for (int o = 4; o; o >>= 1) {
            s2  += __shfl_xor_sync(0xffffffffu, s2,  o);
            ss2 += __shfl_xor_sync(0xffffffffu, ss2, o);
        }
        if (threadIdx.x == 0) {
            float mu  = s2 / (float)M;
            float var = ss2 / (float)M - mu * mu;
            red[0] = mu;
            red[1] = rsqrtf(var + GEPS);
        }
    }
    __syncthreads();
    const float mu = red[0], inv = red[1];
    for (int i = threadIdx.x; i < M; i += blockDim.x) {
        int c = g * CPG + i / NPIX;
        op[i] = (xp[i] - mu) * inv * gamma[c] + beta[c];
    }
}

// ---------------- batched GEMM: Y[b] = W @ X[b] + bias (+res) ---------------
// W:[O,C] row-major, X:[B,C,N], Y:[B,O,N].  64x64 tile, BK=16, 4x4/thread.
__global__ void gemm_wx(const float* __restrict__ W,
                        const float* __restrict__ X,
                        const float* __restrict__ bias,
                        const float* __restrict__ res,
                        float* __restrict__ Y,
                        int O, int C, int N) {
    const int b  = blockIdx.z;
    const int o0 = blockIdx.y * 64;
    const int n0 = blockIdx.x * 64;
    const float* Xb = X + (size_t)b * C * N;

    __shared__ float As[16][68];   // [k][o]  (68 keeps float4 row alignment)
    __shared__ float Bs[16][68];   // [k][n]

    const int tid = threadIdx.x;
    const int ty = tid / 16, tx = tid % 16;
    float acc[4][4] = {};

    for (int c0 = 0; c0 < C; c0 += 16) {
        {   // A load: 64 o-rows x 16 k, transposed into As[k][o]
            int row = tid >> 2, kq = (tid & 3) * 4;
            float4 wv = *(const float4*)(W + (size_t)(o0 + row) * C + c0 + kq);
            As[kq + 0][row] = wv.x; As[kq + 1][row] = wv.y;
            As[kq + 2][row] = wv.z; As[kq + 3][row] = wv.w;
        }
        {   // B load: 16 k-rows x 64 n
            int kk = tid >> 4, nq = (tid & 15) * 4;
            *(float4*)&Bs[kk][nq] =
                *(const float4*)(Xb + (size_t)(c0 + kk) * N + n0 + nq);
        }
        __syncthreads();
        #pragma unroll
        for (int k = 0; k < 16; k++) {
            float a0 = As[k][ty * 4 + 0], a1 = As[k][ty * 4 + 1];
            float a2 = As[k][ty * 4 + 2], a3 = As[k][ty * 4 + 3];
            float b0 = Bs[k][tx * 4 + 0], b1 = Bs[k][tx * 4 + 1];
            float b2 = Bs[k][tx * 4 + 2], b3 = Bs[k][tx * 4 + 3];
            acc[0][0] += a0 * b0; acc[0][1] += a0 * b1; acc[0][2] += a0 * b2; acc[0][3] += a0 * b3;
            acc[1][0] += a1 * b0; acc[1][1] += a1 * b1; acc[1][2] += a1 * b2; acc[1][3] += a1 * b3;
            acc[2][0] += a2 * b0; acc[2][1] += a2 * b1; acc[2][2] += a2 * b2; acc[2][3] += a2 * b3;
            acc[3][0] += a3 * b0; acc[3][1] += a3 * b1; acc[3][2] += a3 * b2; acc[3][3] += a3 * b3;
        }
        __syncthreads();
    }
    #pragma unroll
    for (int i = 0; i < 4; i++) {
        int o = o0 + ty * 4 + i;
        float bv = bias ? bias[o] : 0.f;
        #pragma unroll
        for (int j = 0; j < 4; j++) {
            int n = n0 + tx * 4 + j;
            size_t idx = ((size_t)b * O + o) * N + n;
            float v = acc[i][j] + bv;
            if (res) v += res[idx];
            Y[idx] = v;
        }
    }
}

// ---------------- scores: S[bh][n][m] = scale * sum_c Q[c][n] K[c][m] -------
__global__ void scores_kernel() {
    const int bh = blockIdx.z;
    const int b = bh / HEADS, h = bh % HEADS;
    const float* Q = g_qkv + ((size_t)b * 3 * CCH + 0 * CCH + h * HD) * NPIX;
    const float* K = g_qkv + ((size_t)b * 3 * CCH + 1 * CCH + h * HD) * NPIX;
    const int n0 = blockIdx.y * 64, m0 = blockIdx.x * 64;

    __shared__ float Qs[16][68], Ks[16][68];
    const int tid = threadIdx.x;
    const int ty = tid / 16, tx = tid % 16;
    float acc[4][4] = {};

    for (int c0 = 0; c0 < HD; c0 += 16) {
        int kk = tid >> 4, q4 = (tid & 15) * 4;
        *(float4*)&Qs[kk][q4] = *(const float4*)(Q + (size_t)(c0 + kk) * NPIX + n0 + q4);
        *(float4*)&Ks[kk][q4] = *(const float4*)(K + (size_t)(c0 + kk) * NPIX + m0 + q4);
        __syncthreads();
        #pragma unroll
        for (int k = 0; k < 16; k++) {
            float a0 = Qs[k][ty * 4 + 0], a1 = Qs[k][ty * 4 + 1];
            float a2 = Qs[k][ty * 4 + 2], a3 = Qs[k][ty * 4 + 3];
            float b0 = Ks[k][tx * 4 + 0], b1 = Ks[k][tx * 4 + 1];
            float b2 = Ks[k][tx * 4 + 2], b3 = Ks[k][tx * 4 + 3];
            acc[0][0] += a0 * b0; acc[0][1] += a0 * b1; acc[0][2] += a0 * b2; acc[0][3] += a0 * b3;
            acc[1][0] += a1 * b0; acc[1][1] += a1 * b1; acc[1][2] += a1 * b2; acc[1][3] += a1 * b3;
            acc[2][0] += a2 * b0; acc[2][1] += a2 * b1; acc[2][2] += a2 * b2; acc[2][3] += a2 * b3;
            acc[3][0] += a3 * b0; acc[3][1] += a3 * b1; acc[3][2] += a3 * b2; acc[3][3] += a3 * b3;
        }
        __syncthreads();
    }
    const float scale = 0.088388347648318447f;   // 128^-0.5
    float* Sp = g_S + (size_t)bh * NPIX * NPIX;
    #pragma unroll
    for (int i = 0; i < 4; i++)
        #pragma unroll
        for (int j = 0; j < 4; j++)
            Sp[(size_t)(n0 + ty * 4 + i) * NPIX + m0 + tx * 4 + j] = acc[i][j] * scale;
}

// ---------------- row softmax over m (in place on g_S) ----------------------
__global__ void softmax_kernel() {
    float* p = g_S + (size_t)blockIdx.x * NPIX;
    const int tid = threadIdx.x;                 // 256 threads, 4 elems each
    float4 v = *(float4*)(p + tid * 4);
    float m = fmaxf(fmaxf(v.x, v.y), fmaxf(v.z, v.w));

    __shared__ float red[32];
    #pragma unroll
    for (int o = 16; o; o >>= 1) m = fmaxf(m, __shfl_xor_sync(0xffffffffu, m, o));
    int warp = tid >> 5, lane = tid & 31;
    if (lane == 0) red[warp] = m;
    __syncthreads();
    if (tid < 32) {
        float t = (tid < 8) ? red[tid] : -1e30f;
        #pragma unroll
        for (int o = 4; o; o >>= 1) t = fmaxf(t, __shfl_xor_sync(0xffffffffu, t, o));
        if (tid == 0) red[0] = t;
    }
    __syncthreads();
    const float M = red[0];
    v.x = __expf(v.x - M); v.y = __expf(v.y - M);
    v.z = __expf(v.z - M); v.w = __expf(v.w - M);
    float s = v.x + v.y + v.z + v.w;
    #pragma unroll
    for (int o = 16; o; o >>= 1) s += __shfl_xor_sync(0xffffffffu, s, o);
    if (lane == 0) red[warp] = s;
    __syncthreads();
    if (tid < 32) {
        float t = (tid < 8) ? red[tid] : 0.f;
        #pragma unroll
        for (int o = 4; o; o >>= 1) t += __shfl_xor_sync(0xffffffffu, t, o);
        if (tid == 0) red[0] = t;
    }
    __syncthreads();
    const float inv = 1.f / red[0];
    v.x *= inv; v.y *= inv; v.z *= inv; v.w *= inv;
    *(float4*)(p + tid * 4) = v;
}

// ---------------- AV: O[bh][c][n] = sum_m V[c][m] P[n][m] -------------------
__global__ void av_kernel() {
    const int bh = blockIdx.z;
    const int b = bh / HEADS, h = bh % HEADS;
    const float* V = g_qkv + ((size_t)b * 3 * CCH + 2 * CCH + h * HD) * NPIX;
    const float* P = g_S + (size_t)bh * NPIX * NPIX;
    const int c0 = blockIdx.y * 64, n0 = blockIdx.x * 64;

    __shared__ float Vs[16][68];   // [m][c]
    __shared__ float Ps[16][68];   // [m][n]
    const int tid = threadIdx.x;
    const int ty = tid / 16, tx = tid % 16;
    float acc[4][4] = {};

    for (int m0 = 0; m0 < NPIX; m0 += 16) {
        {
            int ci = tid >> 2, kq = (tid & 3) * 4;
            float4 vv = *(const float4*)(V + (size_t)(c0 + ci) * NPIX + m0 + kq);
            Vs[kq + 0][ci] = vv.x; Vs[kq + 1][ci] = vv.y;
            Vs[kq + 2][ci] = vv.z; Vs[kq + 3][ci] = vv.w;
        }
        {
            int nj = tid >> 2, kq = (tid & 3) * 4;
            float4 pv = *(const float4*)(P + (size_t)(n0 + nj) * NPIX + m0 + kq);
            Ps[kq + 0][nj] = pv.x; Ps[kq + 1][nj] = pv.y;
            Ps[kq + 2][nj] = pv.z; Ps[kq + 3][nj] = pv.w;
        }
        __syncthreads();
        #pragma unroll
        for (int k = 0; k < 16; k++) {
            float a0 = Vs[k][ty * 4 + 0], a1 = Vs[k][ty * 4 + 1];
            float a2 = Vs[k][ty * 4 + 2], a3 = Vs[k][ty * 4 + 3];
            float b0 = Ps[k][tx * 4 + 0], b1 = Ps[k][tx * 4 + 1];
            float b2 = Ps[k][tx * 4 + 2], b3 = Ps[k][tx * 4 + 3];
            acc[0][0] += a0 * b0; acc[0][1] += a0 * b1; acc[0][2] += a0 * b2; acc[0][3] += a0 * b3;
            acc[1][0] += a1 * b0; acc[1][1] += a1 * b1; acc[1][2] += a1 * b2; acc[1][3] += a1 * b3;
            acc[2][0] += a2 * b0; acc[2][1] += a2 * b1; acc[2][2] += a2 * b2; acc[2][3] += a2 * b3;
            acc[3][0] += a3 * b0; acc[3][1] += a3 * b1; acc[3][2] += a3 * b2; acc[3][3] += a3 * b3;
        }
        __syncthreads();
    }
    #pragma unroll
    for (int i = 0; i < 4; i++) {
        int c = h * HD + c0 + ty * 4 + i;
        #pragma unroll
        for (int j = 0; j < 4; j++) {
            int n = n0 + tx * 4 + j;
            g_att[((size_t)b * CCH + c) * NPIX + n] = acc[i][j];
        }
    }
}

// ---------------- launch -----------------------------------------------------
extern "C" void kernel_launch(void* const* d_in, const int* in_sizes, int n_in,
                              void* d_out, int out_size) {
    const float* x      = (const float*)d_in[0];
    const float* gamma  = (const float*)d_in[1];
    const float* beta   = (const float*)d_in[2];
    const float* w_qkv  = (const float*)d_in[3];
    const float* b_qkv  = (const float*)d_in[4];
    const float* w_proj = (const float*)d_in[5];
    const float* b_proj = (const float*)d_in[6];
    float* out = (float*)d_out;

    float *xn, *qkv, *att;
    cudaGetSymbolAddress((void**)&xn,  g_xn);
    cudaGetSymbolAddress((void**)&qkv, g_qkv);
    cudaGetSymbolAddress((void**)&att, g_att);

    // 1) GroupNorm
    gn_kernel<<<BATCH * GROUPS, 256>>>(x, gamma, beta);

    // 2) QKV projection: [1536,512] @ [512,1024] per batch
    gemm_wx<<<dim3(NPIX / 64, (3 * CCH) / 64, BATCH), 256>>>(
        w_qkv, xn, b_qkv, nullptr, qkv, 3 * CCH, CCH, NPIX);

    // 3) attention scores + softmax + AV
    scores_kernel<<<dim3(NPIX / 64, NPIX / 64, BATCH * HEADS), 256>>>();
    softmax_kernel<<<BATCH * HEADS * NPIX, 256>>>();
    av_kernel<<<dim3(NPIX / 64, HD / 64, BATCH * HEADS), 256>>>();

    // 4) proj + bias + residual
    gemm_wx<<<dim3(NPIX / 64, CCH / 64, BATCH), 256>>>(
        w_proj, att, b_proj, x, out, CCH, CCH, NPIX);
}

// round 2
// speedup vs baseline: 2.4669x; 2.4669x over previous
#include <cuda_runtime.h>
#include <cstdint>

#define BATCH   16
#define CCH     512
#define NPIX    1024          // 32*32
#define HEADS   4
#define HD      128           // CCH / HEADS
#define GROUPS  32
#define CPG     (CCH / GROUPS)   // 16
#define GEPS    1e-5f
#define ATT_SCALE 0.088388347648318447f   // 128^-0.5

// ---------------- scratch (device globals; no allocations allowed) ----------
__device__ float g_xn [BATCH * CCH * NPIX];            //  33.5 MB
__device__ float g_qkv[BATCH * 3 * CCH * NPIX];        // 100.7 MB
__device__ float g_S  [(size_t)BATCH * HEADS * NPIX * NPIX];   // 268.4 MB
__device__ float g_att[BATCH * CCH * NPIX];            //  33.5 MB

// ---------------- GroupNorm -------------------------------------------------
__global__ void gn_kernel(const float* __restrict__ x,
                          const float* __restrict__ gamma,
                          const float* __restrict__ beta) {
    const int bg = blockIdx.x;
    const int b  = bg / GROUPS;
    const int g  = bg % GROUPS;
    const int M  = CPG * NPIX;                  // 16384
    const float* xp = x + ((size_t)b * CCH + (size_t)g * CPG) * NPIX;
    float*       op = g_xn + ((size_t)b * CCH + (size_t)g * CPG) * NPIX;

    float s = 0.f, ss = 0.f;
    for (int i = threadIdx.x; i < M; i += blockDim.x) {
        float v = xp[i];
        s += v; ss += v * v;
    }
    __shared__ float red[64];
    #pragma unroll
    for (int o = 16; o; o >>= 1) {
        s  += __shfl_xor_sync(0xffffffffu, s,  o);
        ss += __shfl_xor_sync(0xffffffffu, ss, o);
    }
    const int warp = threadIdx.x >> 5, lane = threadIdx.x & 31;
    if (lane == 0) { red[warp] = s; red[warp + 32] = ss; }
    __syncthreads();
    if (threadIdx.x < 32) {
        float s2  = (threadIdx.x < 8) ? red[threadIdx.x]      : 0.f;
        float ss2 = (threadIdx.x < 8) ? red[threadIdx.x + 32] : 0.f;
        #pragma unroll
        for (int o = 4; o; o >>= 1) {
            s2  += __shfl_xor_sync(0xffffffffu, s2,  o);
            ss2 += __shfl_xor_sync(0xffffffffu, ss2, o);
        }
        if (threadIdx.x == 0) {
            float mu  = s2 / (float)M;
            float var = ss2 / (float)M - mu * mu;
            red[0] = mu;
            red[1] = rsqrtf(var + GEPS);
        }
    }
    __syncthreads();
    const float mu = red[0], inv = red[1];
    for (int i = threadIdx.x; i < M; i += blockDim.x) {
        int c = g * CPG + i / NPIX;
        op[i] = (xp[i] - mu) * inv * gamma[c] + beta[c];
    }
}

// ---------------- tf32 helpers ----------------------------------------------
__device__ __forceinline__ float f32_to_tf32(float f) {
    uint32_t u;
    asm("cvt.rna.tf32.f32 %0, %1;" : "=r"(u) : "f"(f));
    return __uint_as_float(u);
}
__device__ __forceinline__ uint32_t f2u(float f) { return __float_as_uint(f); }

// ---------------- unified tf32 MMA GEMM --------------------------------------
// C[M,N] = A x B per batch z.  Smem canonical layout: As[k][m], Bs[k][n], pad+8.
// TA/TB: 1 => gmem operand is [mn][k] (K contiguous, needs transpose at staging)
//        0 => gmem operand is [k][mn] (mn contiguous, straight copy)
// MODE: 0=QKV (bias), 1=scores (scale), 2=AV, 3=proj (bias+residual)
#define BM 128
#define BN 128
#define BK 32
#define SPAD 8

template<int MODE, int TA, int TB>
__global__ void __launch_bounds__(256, 2)
mma_gemm(const float* __restrict__ Ag, const float* __restrict__ Bg,
         float* __restrict__ Cg,
         const float* __restrict__ bias, const float* __restrict__ res,
         int M, int N, int K, int lda, int ldb) {
    const int z  = blockIdx.z;
    const int m0 = blockIdx.y * BM;
    const int n0 = blockIdx.x * BN;

    size_t Aoff = 0, Boff = 0, Coff = 0;
    if (MODE == 0) {            // QKV: A=w_qkv, B=xn[b], C=qkv[b]
        Boff = (size_t)z * CCH * NPIX;
        Coff = (size_t)z * 3 * CCH * NPIX;
    } else if (MODE == 1) {     // scores: A=Q[bh], B=K[bh], C=S[bh]
        int b = z >> 2, h = z & 3;
        Aoff = ((size_t)b * 3 * CCH + h * HD) * NPIX;
        Boff = ((size_t)b * 3 * CCH + CCH + h * HD) * NPIX;
        Coff = (size_t)z * NPIX * NPIX;
    } else if (MODE == 2) {     // AV: A=V[bh], B=P[bh], C=att[b,h]
        int b = z >> 2, h = z & 3;
        Aoff = ((size_t)b * 3 * CCH + 2 * CCH + h * HD) * NPIX;
        Boff = (size_t)z * NPIX * NPIX;
        Coff = ((size_t)b * CCH + h * HD) * NPIX;
    } else {                    // proj: A=w_proj, B=att[b], C=out[b], res=x[b]
        Boff = (size_t)z * CCH * NPIX;
        Coff = (size_t)z * CCH * NPIX;
    }

    __shared__ float As[BK][BM + SPAD];
    __shared__ float Bs[BK][BN + SPAD];

    const int tid  = threadIdx.x;
    const int lane = tid & 31;
    const int warp = tid >> 5;
    const int g = lane >> 2, t = lane & 3;
    const int wm0 = (warp >> 2) * 64;    // warp tile 64x32
    const int wn0 = (warp & 3) * 32;

    float cfr[4][4][4];
    #pragma unroll
    for (int i = 0; i < 4; i++)
        #pragma unroll
        for (int j = 0; j < 4; j++)
            #pragma unroll
            for (int q = 0; q < 4; q++) cfr[i][j][q] = 0.f;

    for (int kt = 0; kt < K; kt += BK) {
        // ---- stage A ----
        if (TA == 1) {  // A gmem [m][k]
            const float* ap = Ag + Aoff + (size_t)(m0 + (tid >> 1)) * lda + kt + (tid & 1) * 16;
            int mrow = tid >> 1;
            #pragma unroll
            for (int it = 0; it < 4; it++) {
                float4 v = *(const float4*)(ap + it * 4);
                int kq = (tid & 1) * 16 + it * 4;
                As[kq + 0][mrow] = f32_to_tf32(v.x);
                As[kq + 1][mrow] = f32_to_tf32(v.y);
                As[kq + 2][mrow] = f32_to_tf32(v.z);
                As[kq + 3][mrow] = f32_to_tf32(v.w);
            }
        } else {        // A gmem [k][m]
            int r = tid >> 3;
            const float* ap = Ag + Aoff + (size_t)(kt + r) * lda + m0;
            #pragma unroll
            for (int it = 0; it < 4; it++) {
                int cq = ((tid & 7) + it * 8) * 4;
                float4 v = *(const float4*)(ap + cq);
                As[r][cq + 0] = f32_to_tf32(v.x);
                As[r][cq + 1] = f32_to_tf32(v.y);
                As[r][cq + 2] = f32_to_tf32(v.z);
                As[r][cq + 3] = f32_to_tf32(v.w);
            }
        }
        // ---- stage B ----
        if (TB == 1) {  // B gmem [n][k]
            const float* bp = Bg + Boff + (size_t)(n0 + (tid >> 1)) * ldb + kt + (tid & 1) * 16;
            int nrow = tid >> 1;
            #pragma unroll
            for (int it = 0; it < 4; it++) {
                float4 v = *(const float4*)(bp + it * 4);
                int kq = (tid & 1) * 16 + it * 4;
                Bs[kq + 0][nrow] = f32_to_tf32(v.x);
                Bs[kq + 1][nrow] = f32_to_tf32(v.y);
                Bs[kq + 2][nrow] = f32_to_tf32(v.z);
                Bs[kq + 3][nrow] = f32_to_tf32(v.w);
            }
        } else {        // B gmem [k][n]
            int r = tid >> 3;
            const float* bp = Bg + Boff + (size_t)(kt + r) * ldb + n0;
            #pragma unroll
            for (int it = 0; it < 4; it++) {
                int cq = ((tid & 7) + it * 8) * 4;
                float4 v = *(const float4*)(bp + cq);
                Bs[r][cq + 0] = f32_to_tf32(v.x);
                Bs[r][cq + 1] = f32_to_tf32(v.y);
                Bs[r][cq + 2] = f32_to_tf32(v.z);
                Bs[r][cq + 3] = f32_to_tf32(v.w);
            }
        }
        __syncthreads();

        #pragma unroll
        for (int kk = 0; kk < BK; kk += 8) {
            uint32_t afr[4][4], bfr[4][2];
            #pragma unroll
            for (int mi = 0; mi < 4; mi++) {
                int mb = wm0 + mi * 16;
                afr[mi][0] = f2u(As[kk + t    ][mb + g    ]);
                afr[mi][1] = f2u(As[kk + t    ][mb + g + 8]);
                afr[mi][2] = f2u(As[kk + t + 4][mb + g    ]);
                afr[mi][3] = f2u(As[kk + t + 4][mb + g + 8]);
            }
            #pragma unroll
            for (int ni = 0; ni < 4; ni++) {
                int nb = wn0 + ni * 8;
                bfr[ni][0] = f2u(Bs[kk + t    ][nb + g]);
                bfr[ni][1] = f2u(Bs[kk + t + 4][nb + g]);
            }
            #pragma unroll
            for (int mi = 0; mi < 4; mi++)
                #pragma unroll
                for (int ni = 0; ni < 4; ni++) {
                    asm volatile(
                        "mma.sync.aligned.m16n8k8.row.col.f32.tf32.tf32.f32 "
                        "{%0,%1,%2,%3},{%4,%5,%6,%7},{%8,%9},{%0,%1,%2,%3};\n"
                        : "+f"(cfr[mi][ni][0]), "+f"(cfr[mi][ni][1]),
                          "+f"(cfr[mi][ni][2]), "+f"(cfr[mi][ni][3])
                        : "r"(afr[mi][0]), "r"(afr[mi][1]),
                          "r"(afr[mi][2]), "r"(afr[mi][3]),
                          "r"(bfr[ni][0]), "r"(bfr[ni][1]));
                }
        }
        __syncthreads();
    }

    // ---- epilogue ----
    #pragma unroll
    for (int mi = 0; mi < 4; mi++) {
        #pragma unroll
        for (int rr = 0; rr < 2; rr++) {
            int grow = m0 + wm0 + mi * 16 + g + rr * 8;
            float bv = (MODE == 0 || MODE == 3) ? bias[grow] : 0.f;
            #pragma unroll
            for (int ni = 0; ni < 4; ni++) {
                int gcol = n0 + wn0 + ni * 8 + 2 * t;
                size_t idx = Coff + (size_t)grow * N + gcol;
                float v0 = cfr[mi][ni][rr * 2 + 0];
                float v1 = cfr[mi][ni][rr * 2 + 1];
                if (MODE == 1) { v0 *= ATT_SCALE; v1 *= ATT_SCALE; }
                if (MODE == 0 || MODE == 3) { v0 += bv; v1 += bv; }
                if (MODE == 3) { v0 += res[idx]; v1 += res[idx + 1]; }
                Cg[idx]     = v0;
                Cg[idx + 1] = v1;
            }
        }
    }
}

// ---------------- row softmax over m (in place on g_S) ----------------------
__global__ void softmax_kernel() {
    float* p = g_S + (size_t)blockIdx.x * NPIX;
    const int tid = threadIdx.x;                 // 256 threads, 4 elems each
    float4 v = *(float4*)(p + tid * 4);
    float m = fmaxf(fmaxf(v.x, v.y), fmaxf(v.z, v.w));

    __shared__ float red[32];
    #pragma unroll
    for (int o = 16; o; o >>= 1) m = fmaxf(m, __shfl_xor_sync(0xffffffffu, m, o));
    int warp = tid >> 5, lane = tid & 31;
    if (lane == 0) red[warp] = m;
    __syncthreads();
    if (tid < 32) {
        float t = (tid < 8) ? red[tid] : -1e30f;
        #pragma unroll
        for (int o = 4; o; o >>= 1) t = fmaxf(t, __shfl_xor_sync(0xffffffffu, t, o));
        if (tid == 0) red[0] = t;
    }
    __syncthreads();
    const float M = red[0];
    v.x = __expf(v.x - M); v.y = __expf(v.y - M);
    v.z = __expf(v.z - M); v.w = __expf(v.w - M);
    float s = v.x + v.y + v.z + v.w;
    #pragma unroll
    for (int o = 16; o; o >>= 1) s += __shfl_xor_sync(0xffffffffu, s, o);
    if (lane == 0) red[warp] = s;
    __syncthreads();
    if (tid < 32) {
        float t = (tid < 8) ? red[tid] : 0.f;
        #pragma unroll
        for (int o = 4; o; o >>= 1) t += __shfl_xor_sync(0xffffffffu, t, o);
        if (tid == 0) red[0] = t;
    }
    __syncthreads();
    const float inv = 1.f / red[0];
    v.x *= inv; v.y *= inv; v.z *= inv; v.w *= inv;
    *(float4*)(p + tid * 4) = v;
}

// ---------------- launch -----------------------------------------------------
extern "C" void kernel_launch(void* const* d_in, const int* in_sizes, int n_in,
                              void* d_out, int out_size) {
    const float* x      = (const float*)d_in[0];
    const float* gamma  = (const float*)d_in[1];
    const float* beta   = (const float*)d_in[2];
    const float* w_qkv  = (const float*)d_in[3];
    const float* b_qkv  = (const float*)d_in[4];
    const float* w_proj = (const float*)d_in[5];
    const float* b_proj = (const float*)d_in[6];
    float* out = (float*)d_out;

    float *xn, *qkv, *S, *att;
    cudaGetSymbolAddress((void**)&xn,  g_xn);
    cudaGetSymbolAddress((void**)&qkv, g_qkv);
    cudaGetSymbolAddress((void**)&S,   g_S);
    cudaGetSymbolAddress((void**)&att, g_att);

    // 1) GroupNorm
    gn_kernel<<<BATCH * GROUPS, 256>>>(x, gamma, beta);

    // 2) QKV projection: W[1536,512] (TA=1) x xn[512,1024] (TB=0)
    mma_gemm<0, 1, 0><<<dim3(NPIX / BN, 3 * CCH / BM, BATCH), 256>>>(
        w_qkv, xn, qkv, b_qkv, nullptr, 3 * CCH, NPIX, CCH, CCH, NPIX);

    // 3) scores: Q^T (TA=0, A=[k][m]) x K (TB=0, B=[k][n]); K-dim = HD
    mma_gemm<1, 0, 0><<<dim3(NPIX / BN, NPIX / BM, BATCH * HEADS), 256>>>(
        qkv, qkv, S, nullptr, nullptr, NPIX, NPIX, HD, NPIX, NPIX);

    // 4) softmax rows
    softmax_kernel<<<BATCH * HEADS * NPIX, 256>>>();

    // 5) AV: V[128,1024] (TA=1) x P^T (TB=1, B=[n][k]); K-dim = NPIX
    mma_gemm<2, 1, 1><<<dim3(NPIX / BN, HD / BM, BATCH * HEADS), 256>>>(
        qkv, S, att, nullptr, nullptr, HD, NPIX, NPIX, NPIX, NPIX);

    // 6) proj + bias + residual
    mma_gemm<3, 1, 0><<<dim3(NPIX / BN, CCH / BM, BATCH), 256>>>(
        w_proj, att, out, b_proj, x, CCH, NPIX, CCH, CCH, NPIX);
}

// round 7
// speedup vs baseline: 3.6909x; 1.4962x over previous
#include <cuda_runtime.h>
#include <cuda_bf16.h>
#include <cstdint>

#define BATCH   16
#define CCH     512
#define NPIX    1024          // 32*32
#define HEADS   4
#define HD      128           // CCH / HEADS
#define GROUPS  32
#define CPG     (CCH / GROUPS)   // 16
#define GEPS    1e-5f
#define ATT_SCALE 0.088388347648318447f   // 128^-0.5
#define NBH     (BATCH * HEADS)           // 64

// ---------------- scratch (device globals; no allocations allowed) ----------
__device__ float g_xn [BATCH * CCH * NPIX];             //  33.5 MB
__device__ float g_qkv[BATCH * 3 * CCH * NPIX];         // 100.7 MB
__device__ float g_att[BATCH * CCH * NPIX];             //  33.5 MB
__device__ __nv_bfloat16 g_qT[(size_t)NBH * NPIX * HD]; // [bh][q][c], pre-scaled
__device__ __nv_bfloat16 g_kT[(size_t)NBH * NPIX * HD]; // [bh][key][c]
__device__ __nv_bfloat16 g_vb[(size_t)BATCH * CCH * NPIX]; // [b][c][key] bf16

__device__ __forceinline__ uint32_t pack_bf2(float a, float b) {
    __nv_bfloat162 h = __floats2bfloat162_rn(a, b);
    return *(uint32_t*)&h;
}

// ---------------- GroupNorm -------------------------------------------------
__global__ void gn_kernel(const float* __restrict__ x,
                          const float* __restrict__ gamma,
                          const float* __restrict__ beta) {
    const int bg = blockIdx.x;
    const int b  = bg / GROUPS;
    const int g  = bg % GROUPS;
    const int M  = CPG * NPIX;                  // 16384
    const float* xp = x + ((size_t)b * CCH + (size_t)g * CPG) * NPIX;
    float*       op = g_xn + ((size_t)b * CCH + (size_t)g * CPG) * NPIX;

    float s = 0.f, ss = 0.f;
    for (int i = threadIdx.x; i < M; i += blockDim.x) {
        float v = xp[i];
        s += v; ss += v * v;
    }
    __shared__ float red[64];
    #pragma unroll
    for (int o = 16; o; o >>= 1) {
        s  += __shfl_xor_sync(0xffffffffu, s,  o);
        ss += __shfl_xor_sync(0xffffffffu, ss, o);
    }
    const int warp = threadIdx.x >> 5, lane = threadIdx.x & 31;
    if (lane == 0) { red[warp] = s; red[warp + 32] = ss; }
    __syncthreads();
    if (threadIdx.x < 32) {
        float s2  = (threadIdx.x < 8) ? red[threadIdx.x]      : 0.f;
        float ss2 = (threadIdx.x < 8) ? red[threadIdx.x + 32] : 0.f;
        #pragma unroll
        for (int o = 4; o; o >>= 1) {
            s2  += __shfl_xor_sync(0xffffffffu, s2,  o);
            ss2 += __shfl_xor_sync(0xffffffffu, ss2, o);
        }
        if (threadIdx.x == 0) {
            float mu  = s2 / (float)M;
            float var = ss2 / (float)M - mu * mu;
            red[0] = mu;
            red[1] = rsqrtf(var + GEPS);
        }
    }
    __syncthreads();
    const float mu = red[0], inv = red[1];
    for (int i = threadIdx.x; i < M; i += blockDim.x) {
        int c = g * CPG + i / NPIX;
        op[i] = (xp[i] - mu) * inv * gamma[c] + beta[c];
    }
}

// ---------------- tf32 helpers ----------------------------------------------
__device__ __forceinline__ float f32_to_tf32(float f) {
    uint32_t u;
    asm("cvt.rna.tf32.f32 %0, %1;" : "=r"(u) : "f"(f));
    return __uint_as_float(u);
}
__device__ __forceinline__ uint32_t f2u(float f) { return __float_as_uint(f); }

// ---------------- unified tf32 MMA GEMM (QKV / proj) — R2-proven ------------
#define BM 128
#define BN 128
#define BK 32
#define SPAD 8

template<int MODE>
__global__ void __launch_bounds__(256, 2)
mma_gemm(const float* __restrict__ Ag, const float* __restrict__ Bg,
         float* __restrict__ Cg,
         const float* __restrict__ bias, const float* __restrict__ res,
         int M, int N, int K, int lda, int ldb) {
    const int z  = blockIdx.z;
    const int m0 = blockIdx.y * BM;
    const int n0 = blockIdx.x * BN;

    size_t Boff = (size_t)z * CCH * NPIX;
    size_t Coff = (MODE == 0) ? (size_t)z * 3 * CCH * NPIX
                              : (size_t)z * CCH * NPIX;

    __shared__ float As[BK][BM + SPAD];
    __shared__ float Bs[BK][BN + SPAD];

    const int tid  = threadIdx.x;
    const int lane = tid & 31;
    const int warp = tid >> 5;
    const int g = lane >> 2, t = lane & 3;
    const int wm0 = (warp >> 2) * 64;
    const int wn0 = (warp & 3) * 32;

    float cfr[4][4][4];
    #pragma unroll
    for (int i = 0; i < 4; i++)
        #pragma unroll
        for (int j = 0; j < 4; j++)
            #pragma unroll
            for (int q = 0; q < 4; q++) cfr[i][j][q] = 0.f;

    for (int kt = 0; kt < K; kt += BK) {
        {   // A gmem [m][k] (weights)
            const float* ap = Ag + (size_t)(m0 + (tid >> 1)) * lda + kt + (tid & 1) * 16;
            int mrow = tid >> 1;
            #pragma unroll
            for (int it = 0; it < 4; it++) {
                float4 v = *(const float4*)(ap + it * 4);
                int kq = (tid & 1) * 16 + it * 4;
                As[kq + 0][mrow] = f32_to_tf32(v.x);
                As[kq + 1][mrow] = f32_to_tf32(v.y);
                As[kq + 2][mrow] = f32_to_tf32(v.z);
                As[kq + 3][mrow] = f32_to_tf32(v.w);
            }
        }
        {   // B gmem [k][n]
            int r = tid >> 3;
            const float* bp = Bg + Boff + (size_t)(kt + r) * ldb + n0;
            #pragma unroll
            for (int it = 0; it < 4; it++) {
                int cq = ((tid & 7) + it * 8) * 4;
                float4 v = *(const float4*)(bp + cq);
                Bs[r][cq + 0] = f32_to_tf32(v.x);
                Bs[r][cq + 1] = f32_to_tf32(v.y);
                Bs[r][cq + 2] = f32_to_tf32(v.z);
                Bs[r][cq + 3] = f32_to_tf32(v.w);
            }
        }
        __syncthreads();

        #pragma unroll
        for (int kk = 0; kk < BK; kk += 8) {
            uint32_t afr[4][4], bfr[4][2];
            #pragma unroll
            for (int mi = 0; mi < 4; mi++) {
                int mb = wm0 + mi * 16;
                afr[mi][0] = f2u(As[kk + t    ][mb + g    ]);
                afr[mi][1] = f2u(As[kk + t    ][mb + g + 8]);
                afr[mi][2] = f2u(As[kk + t + 4][mb + g    ]);
                afr[mi][3] = f2u(As[kk + t + 4][mb + g + 8]);
            }
            #pragma unroll
            for (int ni = 0; ni < 4; ni++) {
                int nb = wn0 + ni * 8;
                bfr[ni][0] = f2u(Bs[kk + t    ][nb + g]);
                bfr[ni][1] = f2u(Bs[kk + t + 4][nb + g]);
            }
            #pragma unroll
            for (int mi = 0; mi < 4; mi++)
                #pragma unroll
                for (int ni = 0; ni < 4; ni++) {
                    asm volatile(
                        "mma.sync.aligned.m16n8k8.row.col.f32.tf32.tf32.f32 "
                        "{%0,%1,%2,%3},{%4,%5,%6,%7},{%8,%9},{%0,%1,%2,%3};\n"
                        : "+f"(cfr[mi][ni][0]), "+f"(cfr[mi][ni][1]),
                          "+f"(cfr[mi][ni][2]), "+f"(cfr[mi][ni][3])
                        : "r"(afr[mi][0]), "r"(afr[mi][1]),
                          "r"(afr[mi][2]), "r"(afr[mi][3]),
                          "r"(bfr[ni][0]), "r"(bfr[ni][1]));
                }
        }
        __syncthreads();
    }

    #pragma unroll
    for (int mi = 0; mi < 4; mi++) {
        #pragma unroll
        for (int rr = 0; rr < 2; rr++) {
            int grow = m0 + wm0 + mi * 16 + g + rr * 8;
            float bv = bias[grow];
            #pragma unroll
            for (int ni = 0; ni < 4; ni++) {
                int gcol = n0 + wn0 + ni * 8 + 2 * t;
                size_t idx = Coff + (size_t)grow * N + gcol;
                float v0 = cfr[mi][ni][rr * 2 + 0] + bv;
                float v1 = cfr[mi][ni][rr * 2 + 1] + bv;
                if (MODE == 3) { v0 += res[idx]; v1 += res[idx + 1]; }
                Cg[idx]     = v0;
                Cg[idx + 1] = v1;
            }
        }
    }
}

// ---------------- prep: transpose Q,K to [bh][qk][c] bf16 --------------------
// grid (HD/32, NPIX/32, NBH*2), block (32,8). which = z&1 (0=Q scaled, 1=K)
__global__ void prep_qkT() {
    __shared__ float ts[32][33];
    const int z = blockIdx.z;
    const int bh = z >> 1, which = z & 1;
    const int b = bh >> 2, h = bh & 3;
    const int c0 = blockIdx.x * 32, q0 = blockIdx.y * 32;
    const float* src = g_qkv
        + ((size_t)(b * 3 + which) * CCH + h * HD) * NPIX;
    __nv_bfloat16* dst = (which == 0 ? g_qT : g_kT) + (size_t)bh * NPIX * HD;
    const float scale = (which == 0) ? ATT_SCALE : 1.0f;

    #pragma unroll
    for (int i = 0; i < 4; i++) {
        int c = c0 + threadIdx.y + i * 8;
        ts[threadIdx.y + i * 8][threadIdx.x] = src[(size_t)c * NPIX + q0 + threadIdx.x];
    }
    __syncthreads();
    #pragma unroll
    for (int i = 0; i < 4; i++) {
        int q = q0 + threadIdx.y + i * 8;
        dst[(size_t)q * HD + c0 + threadIdx.x] =
            __float2bfloat16(ts[threadIdx.x][threadIdx.y + i * 8] * scale);
    }
}

// ---------------- prep: V fp32 -> bf16 (layout unchanged) --------------------
__global__ void prep_v() {
    const size_t CN = (size_t)CCH * NPIX;
    size_t i = ((size_t)blockIdx.x * blockDim.x + threadIdx.x) * 8;
    size_t b = i / CN, rem = i - b * CN;
    const float* src = g_qkv + (b * 3 + 2) * CN + rem;
    float4 v0 = *(const float4*)(src);
    float4 v1 = *(const float4*)(src + 4);
    uint4 o;
    o.x = pack_bf2(v0.x, v0.y); o.y = pack_bf2(v0.z, v0.w);
    o.z = pack_bf2(v1.x, v1.y); o.w = pack_bf2(v1.z, v1.w);
    *(uint4*)(g_vb + i) = o;
}

// ---------------- flash attention: plain-LDS bf16 mma ------------------------
#define MMA_BF16(c, a, b) \
    asm volatile("mma.sync.aligned.m16n8k16.row.col.f32.bf16.bf16.f32 " \
        "{%0,%1,%2,%3},{%4,%5,%6,%7},{%8,%9},{%0,%1,%2,%3};" \
        : "+f"((c)[0]), "+f"((c)[1]), "+f"((c)[2]), "+f"((c)[3]) \
        : "r"((a)[0]), "r"((a)[1]), "r"((a)[2]), "r"((a)[3]), \
          "r"((b)[0]), "r"((b)[1]))
#define LDW(p) (*(const uint32_t*)(p))

#define FSTR 136                       // bf16 row stride (bank-injective: 4g+t)
#define TILE_B (128 * FSTR * 2)        // 34816 bytes per bf16 tile
#define QS_OFF  0
#define KS_OFF  (TILE_B)
#define VS_OFF  (2 * TILE_B)
#define PS_OFF  (3 * TILE_B)
#define RED_OFF (4 * TILE_B)
#define FLASH_SMEM (4 * TILE_B + 4096)

__global__ void __launch_bounds__(256, 1) flash_kernel() {
    extern __shared__ char smbuf[];
    __nv_bfloat16* Qs = (__nv_bfloat16*)(smbuf + QS_OFF);
    __nv_bfloat16* Ks = (__nv_bfloat16*)(smbuf + KS_OFF);
    __nv_bfloat16* Vs = (__nv_bfloat16*)(smbuf + VS_OFF);
    __nv_bfloat16* Ps = (__nv_bfloat16*)(smbuf + PS_OFF);
    float* redm = (float*)(smbuf + RED_OFF);   // [4][128]
    float* redl = redm + 512;                  // [4][128]
    float* Ot   = (float*)(smbuf + KS_OFF);    // reuse K/V tiles: 128*132 f32

    const int tid = threadIdx.x, lane = tid & 31, warp = tid >> 5;
    const int g = lane >> 2, t = lane & 3;
    const int wm = (warp >> 2) * 64, wn = (warp & 3) * 32;
    const int bh = blockIdx.y, b = bh >> 2, h = bh & 3;
    const int q0 = blockIdx.x * 128;

    const __nv_bfloat16* qsrc = g_qT + (size_t)bh * NPIX * HD + (size_t)q0 * HD;
    const __nv_bfloat16* ksrc = g_kT + (size_t)bh * NPIX * HD;
    const __nv_bfloat16* vsrc = g_vb + ((size_t)b * CCH + h * HD) * NPIX;

    // stage Q: Qs[q][c], q=row, c contiguous
    #pragma unroll
    for (int it = 0; it < 8; it++) {
        int idx = tid + it * 256;
        int row = idx >> 4, col8 = (idx & 15) * 8;
        *(uint4*)(Qs + row * FSTR + col8) = *(const uint4*)(qsrc + row * HD + col8);
    }

    float oacc[4][4][4];
    #pragma unroll
    for (int a = 0; a < 4; a++)
        #pragma unroll
        for (int c = 0; c < 4; c++)
            #pragma unroll
            for (int q = 0; q < 4; q++) oacc[a][c][q] = 0.f;
    float m_run[4][2], l_run[4][2];
    #pragma unroll
    for (int a = 0; a < 4; a++) { m_run[a][0] = m_run[a][1] = -1e30f;
                                  l_run[a][0] = l_run[a][1] = 0.f; }

    for (int kc = 0; kc < 8; kc++) {
        // stage K chunk: Ks[key][c]; V chunk: Vs[c][key]
        #pragma unroll
        for (int it = 0; it < 8; it++) {
            int idx = tid + it * 256;
            int row = idx >> 4, col8 = (idx & 15) * 8;
            *(uint4*)(Ks + row * FSTR + col8) =
                *(const uint4*)(ksrc + (size_t)(kc * 128 + row) * HD + col8);
            *(uint4*)(Vs + row * FSTR + col8) =
                *(const uint4*)(vsrc + (size_t)row * NPIX + kc * 128 + col8);
        }
        __syncthreads();

        // S = Q K^T : rows q (m), cols key (n), k = c
        float sacc[4][4][4];
        #pragma unroll
        for (int a = 0; a < 4; a++)
            #pragma unroll
            for (int c = 0; c < 4; c++)
                #pragma unroll
                for (int q = 0; q < 4; q++) sacc[a][c][q] = 0.f;
        #pragma unroll
        for (int ks = 0; ks < 8; ks++) {
            const int kb = ks * 16;
            uint32_t af[4][4], bf[4][2];
            #pragma unroll
            for (int mi = 0; mi < 4; mi++) {
                const __nv_bfloat16* p = Qs + (wm + mi * 16 + g) * FSTR + kb + 2 * t;
                af[mi][0] = LDW(p);
                af[mi][1] = LDW(p + 8 * FSTR);
                af[mi][2] = LDW(p + 8);
                af[mi][3] = LDW(p + 8 * FSTR + 8);
            }
            #pragma unroll
            for (int ni = 0; ni < 4; ni++) {
                const __nv_bfloat16* p = Ks + (wn + ni * 8 + g) * FSTR + kb + 2 * t;
                bf[ni][0] = LDW(p);
                bf[ni][1] = LDW(p + 8);
            }
            #pragma unroll
            for (int mi = 0; mi < 4; mi++)
                #pragma unroll
                for (int ni = 0; ni < 4; ni++)
                    MMA_BF16(sacc[mi][ni], af[mi], bf[ni]);
        }

        // online softmax: per-row max (rows q = wm+mi*16+g+8rr)
        #pragma unroll
        for (int mi = 0; mi < 4; mi++)
            #pragma unroll
            for (int rr = 0; rr < 2; rr++) {
                float mx = -1e30f;
                #pragma unroll
                for (int ni = 0; ni < 4; ni++)
                    mx = fmaxf(mx, fmaxf(sacc[mi][ni][2 * rr], sacc[mi][ni][2 * rr + 1]));
                mx = fmaxf(mx, __shfl_xor_sync(0xffffffffu, mx, 1));
                mx = fmaxf(mx, __shfl_xor_sync(0xffffffffu, mx, 2));
                if (t == 0) redm[(warp & 3) * 128 + wm + mi * 16 + g + 8 * rr] = mx;
            }
        __syncthreads();

        float mnew[4][2], al[4][2];
        #pragma unroll
        for (int mi = 0; mi < 4; mi++)
            #pragma unroll
            for (int rr = 0; rr < 2; rr++) {
                int r = wm + mi * 16 + g + 8 * rr;
                float mx = fmaxf(fmaxf(redm[r], redm[128 + r]),
                                 fmaxf(redm[256 + r], redm[384 + r]));
                float mn = fmaxf(m_run[mi][rr], mx);
                al[mi][rr]   = __expf(m_run[mi][rr] - mn);
                mnew[mi][rr] = mn;
            }

        // P = exp(S - m) -> Ps[q][key]; partial row sums
        float lloc[4][2] = {};
        #pragma unroll
        for (int mi = 0; mi < 4; mi++)
            #pragma unroll
            for (int ni = 0; ni < 4; ni++)
                #pragma unroll
                for (int rr = 0; rr < 2; rr++) {
                    float p0 = __expf(sacc[mi][ni][2 * rr]     - mnew[mi][rr]);
                    float p1 = __expf(sacc[mi][ni][2 * rr + 1] - mnew[mi][rr]);
                    lloc[mi][rr] += p0 + p1;
                    *(uint32_t*)(Ps + (wm + mi * 16 + g + 8 * rr) * FSTR
                                    + wn + ni * 8 + 2 * t) = pack_bf2(p0, p1);
                }
        #pragma unroll
        for (int mi = 0; mi < 4; mi++)
            #pragma unroll
            for (int rr = 0; rr < 2; rr++) {
                float s = lloc[mi][rr];
                s += __shfl_xor_sync(0xffffffffu, s, 1);
                s += __shfl_xor_sync(0xffffffffu, s, 2);
                if (t == 0) redl[(warp & 3) * 128 + wm + mi * 16 + g + 8 * rr] = s;
            }
        __syncthreads();

        #pragma unroll
        for (int mi = 0; mi < 4; mi++)
            #pragma unroll
            for (int rr = 0; rr < 2; rr++) {
                int r = wm + mi * 16 + g + 8 * rr;
                float cl = redl[r] + redl[128 + r] + redl[256 + r] + redl[384 + r];
                l_run[mi][rr] = l_run[mi][rr] * al[mi][rr] + cl;
                m_run[mi][rr] = mnew[mi][rr];
            }
        // rescale O
        #pragma unroll
        for (int mi = 0; mi < 4; mi++)
            #pragma unroll
            for (int ni = 0; ni < 4; ni++)
                #pragma unroll
                for (int q = 0; q < 4; q++)
                    oacc[mi][ni][q] *= al[mi][q >> 1];

        // O += P V^T : rows q (m), cols c (n), k = key
        #pragma unroll
        for (int ks = 0; ks < 8; ks++) {
            const int kb = ks * 16;
            uint32_t pf[4][4], vf[4][2];
            #pragma unroll
            for (int mi = 0; mi < 4; mi++) {
                const __nv_bfloat16* p = Ps + (wm + mi * 16 + g) * FSTR + kb + 2 * t;
                pf[mi][0] = LDW(p);
                pf[mi][1] = LDW(p + 8 * FSTR);
                pf[mi][2] = LDW(p + 8);
                pf[mi][3] = LDW(p + 8 * FSTR + 8);
            }
            #pragma unroll
            for (int ni = 0; ni < 4; ni++) {
                const __nv_bfloat16* p = Vs + (wn + ni * 8 + g) * FSTR + kb + 2 * t;
                vf[ni][0] = LDW(p);
                vf[ni][1] = LDW(p + 8);
            }
            #pragma unroll
            for (int mi = 0; mi < 4; mi++)
                #pragma unroll
                for (int ni = 0; ni < 4; ni++)
                    MMA_BF16(oacc[mi][ni], pf[mi], vf[ni]);
        }
        __syncthreads();
    }

    // epilogue: O/l -> Ot[c][q] (smem transpose) -> coalesced [c][q] store
    float inv[4][2];
    #pragma unroll
    for (int mi = 0; mi < 4; mi++) {
        inv[mi][0] = 1.f / l_run[mi][0];
        inv[mi][1] = 1.f / l_run[mi][1];
    }
    #pragma unroll
    for (int mi = 0; mi < 4; mi++)
        #pragma unroll
        for (int ni = 0; ni < 4; ni++)
            #pragma unroll
            for (int q = 0; q < 4; q++) {
                int col = wn + ni * 8 + 2 * t + (q & 1);          // c
                int row = wm + mi * 16 + g + 8 * (q >> 1);        // q
                Ot[col * 132 + row] = oacc[mi][ni][q] * inv[mi][q >> 1];
            }
    __syncthreads();
    float* og = g_att + ((size_t)b * CCH + h * HD) * NPIX + q0;
    #pragma unroll
    for (int it = 0; it < 16; it++) {
        int idx = tid + it * 256;
        int c = idx >> 5, q4 = (idx & 31) << 2;
        *(float4*)(og + (size_t)c * NPIX + q4) = *(const float4*)(Ot + c * 132 + q4);
    }
}

// ---------------- launch -----------------------------------------------------
extern "C" void kernel_launch(void* const* d_in, const int* in_sizes, int n_in,
                              void* d_out, int out_size) {
    const float* x      = (const float*)d_in[0];
    const float* gamma  = (const float*)d_in[1];
    const float* beta   = (const float*)d_in[2];
    const float* w_qkv  = (const float*)d_in[3];
    const float* b_qkv  = (const float*)d_in[4];
    const float* w_proj = (const float*)d_in[5];
    const float* b_proj = (const float*)d_in[6];
    float* out = (float*)d_out;

    float *xn, *qkv, *att;
    cudaGetSymbolAddress((void**)&xn,  g_xn);
    cudaGetSymbolAddress((void**)&qkv, g_qkv);
    cudaGetSymbolAddress((void**)&att, g_att);

    cudaFuncSetAttribute(flash_kernel,
        cudaFuncAttributeMaxDynamicSharedMemorySize, FLASH_SMEM);

    // 1) GroupNorm
    gn_kernel<<<BATCH * GROUPS, 256>>>(x, gamma, beta);

    // 2) QKV projection (tf32)
    mma_gemm<0><<<dim3(NPIX / BN, 3 * CCH / BM, BATCH), 256>>>(
        w_qkv, xn, qkv, b_qkv, nullptr, 3 * CCH, NPIX, CCH, CCH, NPIX);

    // 3) prep: Q/K transpose + scale, V bf16 convert
    prep_qkT<<<dim3(HD / 32, NPIX / 32, NBH * 2), dim3(32, 8)>>>();
    prep_v<<<(BATCH * CCH * NPIX) / (256 * 8), 256>>>();

    // 4) fused flash attention (bf16, plain-LDS fragments)
    flash_kernel<<<dim3(NPIX / 128, NBH), 256, FLASH_SMEM>>>();

    // 5) proj + bias + residual (tf32)
    mma_gemm<3><<<dim3(NPIX / BN, CCH / BM, BATCH), 256>>>(
        w_proj, att, out, b_proj, x, CCH, NPIX, CCH, CCH, NPIX);
}

// round 8
// speedup vs baseline: 4.2028x; 1.1387x over previous
#include <cuda_runtime.h>
#include <cuda_bf16.h>
#include <cstdint>

#define BATCH   16
#define CCH     512
#define NPIX    1024          // 32*32
#define HEADS   4
#define HD      128           // CCH / HEADS
#define GROUPS  32
#define CPG     (CCH / GROUPS)   // 16
#define GEPS    1e-5f
#define ATT_SCALE 0.088388347648318447f   // 128^-0.5
#define NBH     (BATCH * HEADS)           // 64

// ---------------- scratch (device globals; no allocations allowed) ----------
__device__ float g_xn [BATCH * CCH * NPIX];             //  33.5 MB
__device__ float g_qkv[BATCH * 3 * CCH * NPIX];         // 100.7 MB
__device__ float g_att[BATCH * CCH * NPIX];             //  33.5 MB
__device__ __nv_bfloat16 g_qT[(size_t)NBH * NPIX * HD]; // [bh][q][c], pre-scaled
__device__ __nv_bfloat16 g_kT[(size_t)NBH * NPIX * HD]; // [bh][key][c]
__device__ __nv_bfloat16 g_vb[(size_t)BATCH * CCH * NPIX]; // [b][c][key] bf16

__device__ __forceinline__ uint32_t pack_bf2(float a, float b) {
    __nv_bfloat162 h = __floats2bfloat162_rn(a, b);
    return *(uint32_t*)&h;
}

// ---------------- GroupNorm -------------------------------------------------
__global__ void gn_kernel(const float* __restrict__ x,
                          const float* __restrict__ gamma,
                          const float* __restrict__ beta) {
    const int bg = blockIdx.x;
    const int b  = bg / GROUPS;
    const int g  = bg % GROUPS;
    const int M  = CPG * NPIX;                  // 16384
    const float* xp = x + ((size_t)b * CCH + (size_t)g * CPG) * NPIX;
    float*       op = g_xn + ((size_t)b * CCH + (size_t)g * CPG) * NPIX;

    float s = 0.f, ss = 0.f;
    for (int i = threadIdx.x; i < M; i += blockDim.x) {
        float v = xp[i];
        s += v; ss += v * v;
    }
    __shared__ float red[64];
    #pragma unroll
    for (int o = 16; o; o >>= 1) {
        s  += __shfl_xor_sync(0xffffffffu, s,  o);
        ss += __shfl_xor_sync(0xffffffffu, ss, o);
    }
    const int warp = threadIdx.x >> 5, lane = threadIdx.x & 31;
    if (lane == 0) { red[warp] = s; red[warp + 32] = ss; }
    __syncthreads();
    if (threadIdx.x < 32) {
        float s2  = (threadIdx.x < 8) ? red[threadIdx.x]      : 0.f;
        float ss2 = (threadIdx.x < 8) ? red[threadIdx.x + 32] : 0.f;
        #pragma unroll
        for (int o = 4; o; o >>= 1) {
            s2  += __shfl_xor_sync(0xffffffffu, s2,  o);
            ss2 += __shfl_xor_sync(0xffffffffu, ss2, o);
        }
        if (threadIdx.x == 0) {
            float mu  = s2 / (float)M;
            float var = ss2 / (float)M - mu * mu;
            red[0] = mu;
            red[1] = rsqrtf(var + GEPS);
        }
    }
    __syncthreads();
    const float mu = red[0], inv = red[1];
    for (int i = threadIdx.x; i < M; i += blockDim.x) {
        int c = g * CPG + i / NPIX;
        op[i] = (xp[i] - mu) * inv * gamma[c] + beta[c];
    }
}

// ---------------- bf16 MMA GEMM (QKV / proj) --------------------------------
// C[M,N] = W[M,K] @ X[K,N] per batch z, bf16 inputs, fp32 accum.
// Smem word layout (k-pairs): As[m][k/2], Bs[n][k/2], row stride SW=20 words.
// Fragment mapping (empirically proven in flash_kernel):
//   a0=(g,2t) a1=(g+8,2t) a2=(g,2t+8) a3=(g+8,2t+8); b0=(2t,g) b1=(2t+8,g)
#define BM 128
#define BN 128
#define BK 32
#define SW 20              // words per smem row (16 data + 4 pad)

#define MMA_BF16(c, a, b) \
    asm volatile("mma.sync.aligned.m16n8k16.row.col.f32.bf16.bf16.f32 " \
        "{%0,%1,%2,%3},{%4,%5,%6,%7},{%8,%9},{%0,%1,%2,%3};" \
        : "+f"((c)[0]), "+f"((c)[1]), "+f"((c)[2]), "+f"((c)[3]) \
        : "r"((a)[0]), "r"((a)[1]), "r"((a)[2]), "r"((a)[3]), \
          "r"((b)[0]), "r"((b)[1]))

template<int MODE>
__global__ void __launch_bounds__(256, 2)
bf16_gemm(const float* __restrict__ Wg, const float* __restrict__ Xg,
          float* __restrict__ Cg,
          const float* __restrict__ bias, const float* __restrict__ res,
          int M, int N, int K, int lda, int ldb) {
    const int z  = blockIdx.z;
    const int m0 = blockIdx.y * BM;
    const int n0 = blockIdx.x * BN;

    const size_t Boff = (size_t)z * CCH * NPIX;
    const size_t Coff = (MODE == 0) ? (size_t)z * 3 * CCH * NPIX
                                    : (size_t)z * CCH * NPIX;

    __shared__ uint32_t As[BM * SW];
    __shared__ uint32_t Bs[BN * SW];

    const int tid  = threadIdx.x;
    const int lane = tid & 31;
    const int warp = tid >> 5;
    const int g = lane >> 2, t = lane & 3;
    const int wm0 = (warp >> 2) * 64;    // warp tile 64x32
    const int wn0 = (warp & 3) * 32;

    float cfr[4][4][4];
    #pragma unroll
    for (int i = 0; i < 4; i++)
        #pragma unroll
        for (int j = 0; j < 4; j++)
            #pragma unroll
            for (int q = 0; q < 4; q++) cfr[i][j][q] = 0.f;

    const int amr  = tid >> 1;             // A staging row
    const int akw  = (tid & 1) * 8;        // A staging word offset (16 k)
    const int bkp  = tid >> 5;             // B staging k-pair base (0..7)
    const int bln  = tid & 31;             // B staging lane n

    for (int kt = 0; kt < K; kt += BK) {
        {   // stage A: W[m][k] row-major -> As[m][k/2] words (straight copy)
            const float* ap = Wg + (size_t)(m0 + amr) * lda + kt + akw * 2;
            uint32_t buf[8];
            #pragma unroll
            for (int it = 0; it < 4; it++) {
                float4 v = *(const float4*)(ap + it * 4);
                buf[it * 2 + 0] = pack_bf2(v.x, v.y);
                buf[it * 2 + 1] = pack_bf2(v.z, v.w);
            }
            uint32_t* dst = As + amr * SW + akw;
            *(uint4*)(dst)     = *(uint4*)(buf);
            *(uint4*)(dst + 4) = *(uint4*)(buf + 4);
        }
        {   // stage B: X[k][n] (n contig) -> Bs[n][k/2] words (transpose)
            #pragma unroll
            for (int half = 0; half < 2; half++) {
                int kp = bkp + half * 8;            // word index in row
                const float* r0 = Xg + Boff + (size_t)(kt + 2 * kp) * ldb + n0;
                const float* r1 = r0 + ldb;
                #pragma unroll
                for (int c = 0; c < 4; c++) {
                    int n = bln + 32 * c;
                    Bs[n * SW + kp] = pack_bf2(r0[n], r1[n]);
                }
            }
        }
        __syncthreads();

        #pragma unroll
        for (int kk = 0; kk < 2; kk++) {       // two k16 steps per BK=32
            const int wb = kk * 8;
            uint32_t af[4][4], bf[4][2];
            #pragma unroll
            for (int mi = 0; mi < 4; mi++) {
                const uint32_t* p = As + (wm0 + mi * 16 + g) * SW + wb + t;
                af[mi][0] = p[0];
                af[mi][1] = p[8 * SW];
                af[mi][2] = p[4];
                af[mi][3] = p[8 * SW + 4];
            }
            #pragma unroll
            for (int ni = 0; ni < 4; ni++) {
                const uint32_t* p = Bs + (wn0 + ni * 8 + g) * SW + wb + t;
                bf[ni][0] = p[0];
                bf[ni][1] = p[4];
            }
            #pragma unroll
            for (int mi = 0; mi < 4; mi++)
                #pragma unroll
                for (int ni = 0; ni < 4; ni++)
                    MMA_BF16(cfr[mi][ni], af[mi], bf[ni]);
        }
        __syncthreads();
    }

    #pragma unroll
    for (int mi = 0; mi < 4; mi++) {
        #pragma unroll
        for (int rr = 0; rr < 2; rr++) {
            int grow = m0 + wm0 + mi * 16 + g + rr * 8;
            float bv = bias[grow];
            #pragma unroll
            for (int ni = 0; ni < 4; ni++) {
                int gcol = n0 + wn0 + ni * 8 + 2 * t;
                size_t idx = Coff + (size_t)grow * N + gcol;
                float v0 = cfr[mi][ni][rr * 2 + 0] + bv;
                float v1 = cfr[mi][ni][rr * 2 + 1] + bv;
                if (MODE == 3) { v0 += res[idx]; v1 += res[idx + 1]; }
                Cg[idx]     = v0;
                Cg[idx + 1] = v1;
            }
        }
    }
}

// ---------------- prep: transpose Q,K to [bh][qk][c] bf16 --------------------
__global__ void prep_qkT() {
    __shared__ float ts[32][33];
    const int z = blockIdx.z;
    const int bh = z >> 1, which = z & 1;
    const int b = bh >> 2, h = bh & 3;
    const int c0 = blockIdx.x * 32, q0 = blockIdx.y * 32;
    const float* src = g_qkv
        + ((size_t)(b * 3 + which) * CCH + h * HD) * NPIX;
    __nv_bfloat16* dst = (which == 0 ? g_qT : g_kT) + (size_t)bh * NPIX * HD;
    const float scale = (which == 0) ? ATT_SCALE : 1.0f;

    #pragma unroll
    for (int i = 0; i < 4; i++) {
        int c = c0 + threadIdx.y + i * 8;
        ts[threadIdx.y + i * 8][threadIdx.x] = src[(size_t)c * NPIX + q0 + threadIdx.x];
    }
    __syncthreads();
    #pragma unroll
    for (int i = 0; i < 4; i++) {
        int q = q0 + threadIdx.y + i * 8;
        dst[(size_t)q * HD + c0 + threadIdx.x] =
            __float2bfloat16(ts[threadIdx.x][threadIdx.y + i * 8] * scale);
    }
}

// ---------------- prep: V fp32 -> bf16 (layout unchanged) --------------------
__global__ void prep_v() {
    const size_t CN = (size_t)CCH * NPIX;
    size_t i = ((size_t)blockIdx.x * blockDim.x + threadIdx.x) * 8;
    size_t b = i / CN, rem = i - b * CN;
    const float* src = g_qkv + (b * 3 + 2) * CN + rem;
    float4 v0 = *(const float4*)(src);
    float4 v1 = *(const float4*)(src + 4);
    uint4 o;
    o.x = pack_bf2(v0.x, v0.y); o.y = pack_bf2(v0.z, v0.w);
    o.z = pack_bf2(v1.x, v1.y); o.w = pack_bf2(v1.z, v1.w);
    *(uint4*)(g_vb + i) = o;
}

// ---------------- flash attention: plain-LDS bf16 mma (R7-proven) -----------
#define LDW(p) (*(const uint32_t*)(p))
#define FSTR 136
#define TILE_B (128 * FSTR * 2)
#define QS_OFF  0
#define KS_OFF  (TILE_B)
#define VS_OFF  (2 * TILE_B)
#define PS_OFF  (3 * TILE_B)
#define RED_OFF (4 * TILE_B)
#define FLASH_SMEM (4 * TILE_B + 4096)

__global__ void __launch_bounds__(256, 1) flash_kernel() {
    extern __shared__ char smbuf[];
    __nv_bfloat16* Qs = (__nv_bfloat16*)(smbuf + QS_OFF);
    __nv_bfloat16* Ks = (__nv_bfloat16*)(smbuf + KS_OFF);
    __nv_bfloat16* Vs = (__nv_bfloat16*)(smbuf + VS_OFF);
    __nv_bfloat16* Ps = (__nv_bfloat16*)(smbuf + PS_OFF);
    float* redm = (float*)(smbuf + RED_OFF);
    float* redl = redm + 512;
    float* Ot   = (float*)(smbuf + KS_OFF);

    const int tid = threadIdx.x, lane = tid & 31, warp = tid >> 5;
    const int g = lane >> 2, t = lane & 3;
    const int wm = (warp >> 2) * 64, wn = (warp & 3) * 32;
    const int bh = blockIdx.y, b = bh >> 2, h = bh & 3;
    const int q0 = blockIdx.x * 128;

    const __nv_bfloat16* qsrc = g_qT + (size_t)bh * NPIX * HD + (size_t)q0 * HD;
    const __nv_bfloat16* ksrc = g_kT + (size_t)bh * NPIX * HD;
    const __nv_bfloat16* vsrc = g_vb + ((size_t)b * CCH + h * HD) * NPIX;

    #pragma unroll
    for (int it = 0; it < 8; it++) {
        int idx = tid + it * 256;
        int row = idx >> 4, col8 = (idx & 15) * 8;
        *(uint4*)(Qs + row * FSTR + col8) = *(const uint4*)(qsrc + row * HD + col8);
    }

    float oacc[4][4][4];
    #pragma unroll
    for (int a = 0; a < 4; a++)
        #pragma unroll
        for (int c = 0; c < 4; c++)
            #pragma unroll
            for (int q = 0; q < 4; q++) oacc[a][c][q] = 0.f;
    float m_run[4][2], l_run[4][2];
    #pragma unroll
    for (int a = 0; a < 4; a++) { m_run[a][0] = m_run[a][1] = -1e30f;
                                  l_run[a][0] = l_run[a][1] = 0.f; }

    for (int kc = 0; kc < 8; kc++) {
        #pragma unroll
        for (int it = 0; it < 8; it++) {
            int idx = tid + it * 256;
            int row = idx >> 4, col8 = (idx & 15) * 8;
            *(uint4*)(Ks + row * FSTR + col8) =
                *(const uint4*)(ksrc + (size_t)(kc * 128 + row) * HD + col8);
            *(uint4*)(Vs + row * FSTR + col8) =
                *(const uint4*)(vsrc + (size_t)row * NPIX + kc * 128 + col8);
        }
        __syncthreads();

        float sacc[4][4][4];
        #pragma unroll
        for (int a = 0; a < 4; a++)
            #pragma unroll
            for (int c = 0; c < 4; c++)
                #pragma unroll
                for (int q = 0; q < 4; q++) sacc[a][c][q] = 0.f;
        #pragma unroll
        for (int ks = 0; ks < 8; ks++) {
            const int kb = ks * 16;
            uint32_t af[4][4], bf[4][2];
            #pragma unroll
            for (int mi = 0; mi < 4; mi++) {
                const __nv_bfloat16* p = Qs + (wm + mi * 16 + g) * FSTR + kb + 2 * t;
                af[mi][0] = LDW(p);
                af[mi][1] = LDW(p + 8 * FSTR);
                af[mi][2] = LDW(p + 8);
                af[mi][3] = LDW(p + 8 * FSTR + 8);
            }
            #pragma unroll
            for (int ni = 0; ni < 4; ni++) {
                const __nv_bfloat16* p = Ks + (wn + ni * 8 + g) * FSTR + kb + 2 * t;
                bf[ni][0] = LDW(p);
                bf[ni][1] = LDW(p + 8);
            }
            #pragma unroll
            for (int mi = 0; mi < 4; mi++)
                #pragma unroll
                for (int ni = 0; ni < 4; ni++)
                    MMA_BF16(sacc[mi][ni], af[mi], bf[ni]);
        }

        #pragma unroll
        for (int mi = 0; mi < 4; mi++)
            #pragma unroll
            for (int rr = 0; rr < 2; rr++) {
                float mx = -1e30f;
                #pragma unroll
                for (int ni = 0; ni < 4; ni++)
                    mx = fmaxf(mx, fmaxf(sacc[mi][ni][2 * rr], sacc[mi][ni][2 * rr + 1]));
                mx = fmaxf(mx, __shfl_xor_sync(0xffffffffu, mx, 1));
                mx = fmaxf(mx, __shfl_xor_sync(0xffffffffu, mx, 2));
                if (t == 0) redm[(warp & 3) * 128 + wm + mi * 16 + g + 8 * rr] = mx;
            }
        __syncthreads();

        float mnew[4][2], al[4][2];
        #pragma unroll
        for (int mi = 0; mi < 4; mi++)
            #pragma unroll
            for (int rr = 0; rr < 2; rr++) {
                int r = wm + mi * 16 + g + 8 * rr;
                float mx = fmaxf(fmaxf(redm[r], redm[128 + r]),
                                 fmaxf(redm[256 + r], redm[384 + r]));
                float mn = fmaxf(m_run[mi][rr], mx);
                al[mi][rr]   = __expf(m_run[mi][rr] - mn);
                mnew[mi][rr] = mn;
            }

        float lloc[4][2] = {};
        #pragma unroll
        for (int mi = 0; mi < 4; mi++)
            #pragma unroll
            for (int ni = 0; ni < 4; ni++)
                #pragma unroll
                for (int rr = 0; rr < 2; rr++) {
                    float p0 = __expf(sacc[mi][ni][2 * rr]     - mnew[mi][rr]);
                    float p1 = __expf(sacc[mi][ni][2 * rr + 1] - mnew[mi][rr]);
                    lloc[mi][rr] += p0 + p1;
                    *(uint32_t*)(Ps + (wm + mi * 16 + g + 8 * rr) * FSTR
                                    + wn + ni * 8 + 2 * t) = pack_bf2(p0, p1);
                }
        #pragma unroll
        for (int mi = 0; mi < 4; mi++)
            #pragma unroll
            for (int rr = 0; rr < 2; rr++) {
                float s = lloc[mi][rr];
                s += __shfl_xor_sync(0xffffffffu, s, 1);
                s += __shfl_xor_sync(0xffffffffu, s, 2);
                if (t == 0) redl[(warp & 3) * 128 + wm + mi * 16 + g + 8 * rr] = s;
            }
        __syncthreads();

        #pragma unroll
        for (int mi = 0; mi < 4; mi++)
            #pragma unroll
            for (int rr = 0; rr < 2; rr++) {
                int r = wm + mi * 16 + g + 8 * rr;
                float cl = redl[r] + redl[128 + r] + redl[256 + r] + redl[384 + r];
                l_run[mi][rr] = l_run[mi][rr] * al[mi][rr] + cl;
                m_run[mi][rr] = mnew[mi][rr];
            }
        #pragma unroll
        for (int mi = 0; mi < 4; mi++)
            #pragma unroll
            for (int ni = 0; ni < 4; ni++)
                #pragma unroll
                for (int q = 0; q < 4; q++)
                    oacc[mi][ni][q] *= al[mi][q >> 1];

        #pragma unroll
        for (int ks = 0; ks < 8; ks++) {
            const int kb = ks * 16;
            uint32_t pf[4][4], vf[4][2];
            #pragma unroll
            for (int mi = 0; mi < 4; mi++) {
                const __nv_bfloat16* p = Ps + (wm + mi * 16 + g) * FSTR + kb + 2 * t;
                pf[mi][0] = LDW(p);
                pf[mi][1] = LDW(p + 8 * FSTR);
                pf[mi][2] = LDW(p + 8);
                pf[mi][3] = LDW(p + 8 * FSTR + 8);
            }
            #pragma unroll
            for (int ni = 0; ni < 4; ni++) {
                const __nv_bfloat16* p = Vs + (wn + ni * 8 + g) * FSTR + kb + 2 * t;
                vf[ni][0] = LDW(p);
                vf[ni][1] = LDW(p + 8);
            }
            #pragma unroll
            for (int mi = 0; mi < 4; mi++)
                #pragma unroll
                for (int ni = 0; ni < 4; ni++)
                    MMA_BF16(oacc[mi][ni], pf[mi], vf[ni]);
        }
        __syncthreads();
    }

    float inv[4][2];
    #pragma unroll
    for (int mi = 0; mi < 4; mi++) {
        inv[mi][0] = 1.f / l_run[mi][0];
        inv[mi][1] = 1.f / l_run[mi][1];
    }
    #pragma unroll
    for (int mi = 0; mi < 4; mi++)
        #pragma unroll
        for (int ni = 0; ni < 4; ni++)
            #pragma unroll
            for (int q = 0; q < 4; q++) {
                int col = wn + ni * 8 + 2 * t + (q & 1);
                int row = wm + mi * 16 + g + 8 * (q >> 1);
                Ot[col * 132 + row] = oacc[mi][ni][q] * inv[mi][q >> 1];
            }
    __syncthreads();
    float* og = g_att + ((size_t)b * CCH + h * HD) * NPIX + q0;
    #pragma unroll
    for (int it = 0; it < 16; it++) {
        int idx = tid + it * 256;
        int c = idx >> 5, q4 = (idx & 31) << 2;
        *(float4*)(og + (size_t)c * NPIX + q4) = *(const float4*)(Ot + c * 132 + q4);
    }
}

// ---------------- launch -----------------------------------------------------
extern "C" void kernel_launch(void* const* d_in, const int* in_sizes, int n_in,
                              void* d_out, int out_size) {
    const float* x      = (const float*)d_in[0];
    const float* gamma  = (const float*)d_in[1];
    const float* beta   = (const float*)d_in[2];
    const float* w_qkv  = (const float*)d_in[3];
    const float* b_qkv  = (const float*)d_in[4];
    const float* w_proj = (const float*)d_in[5];
    const float* b_proj = (const float*)d_in[6];
    float* out = (float*)d_out;

    float *xn, *qkv, *att;
    cudaGetSymbolAddress((void**)&xn,  g_xn);
    cudaGetSymbolAddress((void**)&qkv, g_qkv);
    cudaGetSymbolAddress((void**)&att, g_att);

    cudaFuncSetAttribute(flash_kernel,
        cudaFuncAttributeMaxDynamicSharedMemorySize, FLASH_SMEM);

    // 1) GroupNorm
    gn_kernel<<<BATCH * GROUPS, 256>>>(x, gamma, beta);

    // 2) QKV projection (bf16)
    bf16_gemm<0><<<dim3(NPIX / BN, 3 * CCH / BM, BATCH), 256>>>(
        w_qkv, xn, qkv, b_qkv, nullptr, 3 * CCH, NPIX, CCH, CCH, NPIX);

    // 3) prep: Q/K transpose + scale, V bf16 convert
    prep_qkT<<<dim3(HD / 32, NPIX / 32, NBH * 2), dim3(32, 8)>>>();
    prep_v<<<(BATCH * CCH * NPIX) / (256 * 8), 256>>>();

    // 4) fused flash attention (bf16)
    flash_kernel<<<dim3(NPIX / 128, NBH), 256, FLASH_SMEM>>>();

    // 5) proj + bias + residual (bf16)
    bf16_gemm<3><<<dim3(NPIX / BN, CCH / BM, BATCH), 256>>>(
        w_proj, att, out, b_proj, x, CCH, NPIX, CCH, CCH, NPIX);
}

// round 9
// speedup vs baseline: 4.4595x; 1.0611x over previous
#include <cuda_runtime.h>
#include <cuda_bf16.h>
#include <cstdint>

#define BATCH   16
#define CCH     512
#define NPIX    1024          // 32*32
#define HEADS   4
#define HD      128           // CCH / HEADS
#define GROUPS  32
#define CPG     (CCH / GROUPS)   // 16
#define GEPS    1e-5f
#define ATT_SCALE 0.088388347648318447f   // 128^-0.5
#define NBH     (BATCH * HEADS)           // 64

// ---------------- scratch (device globals; no allocations allowed) ----------
__device__ float g_att[BATCH * CCH * NPIX];                 // 33.5 MB fp32
__device__ float g_gnmu [BATCH * GROUPS];
__device__ float g_gninv[BATCH * GROUPS];
__device__ __nv_bfloat16 g_qc[(size_t)BATCH * CCH * NPIX];  // [b][c][q], scaled
__device__ __nv_bfloat16 g_kc[(size_t)BATCH * CCH * NPIX];  // [b][c][q]
__device__ __nv_bfloat16 g_vb[(size_t)BATCH * CCH * NPIX];  // [b][c][key]
__device__ __nv_bfloat16 g_qT[(size_t)NBH * NPIX * HD];     // [bh][q][c]
__device__ __nv_bfloat16 g_kT[(size_t)NBH * NPIX * HD];     // [bh][key][c]

__device__ __forceinline__ uint32_t pack_bf2(float a, float b) {
    __nv_bfloat162 h = __floats2bfloat162_rn(a, b);
    return *(uint32_t*)&h;
}

// ---------------- GroupNorm stats only ---------------------------------------
__global__ void gn_stats(const float* __restrict__ x) {
    const int bg = blockIdx.x;
    const int b  = bg / GROUPS;
    const int g  = bg % GROUPS;
    const int M  = CPG * NPIX;                  // 16384
    const float* xp = x + ((size_t)b * CCH + (size_t)g * CPG) * NPIX;

    float s = 0.f, ss = 0.f;
    for (int i = threadIdx.x; i < M; i += blockDim.x) {
        float v = xp[i];
        s += v; ss += v * v;
    }
    __shared__ float red[64];
    #pragma unroll
    for (int o = 16; o; o >>= 1) {
        s  += __shfl_xor_sync(0xffffffffu, s,  o);
        ss += __shfl_xor_sync(0xffffffffu, ss, o);
    }
    const int warp = threadIdx.x >> 5, lane = threadIdx.x & 31;
    if (lane == 0) { red[warp] = s; red[warp + 32] = ss; }
    __syncthreads();
    if (threadIdx.x == 0) {
        float s2 = 0.f, ss2 = 0.f;
        #pragma unroll
        for (int i = 0; i < 8; i++) { s2 += red[i]; ss2 += red[i + 32]; }
        float mu  = s2 / (float)M;
        float var = ss2 / (float)M - mu * mu;
        g_gnmu[bg]  = mu;
        g_gninv[bg] = rsqrtf(var + GEPS);
    }
}

// ---------------- bf16 MMA GEMM ----------------------------------------------
// MODE 0: QKV — B-staging applies GroupNorm to x; epilogue writes bf16 Q/K/V.
// MODE 3: proj — plain B; epilogue adds bias + residual, fp32 out.
#define BM 128
#define BN 128
#define BK 32
#define SW 20

#define MMA_BF16(c, a, b) \
    asm volatile("mma.sync.aligned.m16n8k16.row.col.f32.bf16.bf16.f32 " \
        "{%0,%1,%2,%3},{%4,%5,%6,%7},{%8,%9},{%0,%1,%2,%3};" \
        : "+f"((c)[0]), "+f"((c)[1]), "+f"((c)[2]), "+f"((c)[3]) \
        : "r"((a)[0]), "r"((a)[1]), "r"((a)[2]), "r"((a)[3]), \
          "r"((b)[0]), "r"((b)[1]))

template<int MODE>
__global__ void __launch_bounds__(256, 2)
bf16_gemm(const float* __restrict__ Wg, const float* __restrict__ Xg,
          float* __restrict__ Cg,
          const float* __restrict__ bias, const float* __restrict__ res,
          const float* __restrict__ gamma, const float* __restrict__ beta,
          int M, int N, int K, int lda, int ldb) {
    const int z  = blockIdx.z;
    const int m0 = blockIdx.y * BM;
    const int n0 = blockIdx.x * BN;
    const size_t Boff = (size_t)z * CCH * NPIX;

    __shared__ uint32_t As[BM * SW];
    __shared__ uint32_t Bs[BN * SW];
    __shared__ float s_mu[GROUPS], s_inv[GROUPS];
    __shared__ float s_gam[CCH], s_bet[CCH];

    const int tid  = threadIdx.x;
    const int lane = tid & 31;
    const int warp = tid >> 5;
    const int g = lane >> 2, t = lane & 3;
    const int wm0 = (warp >> 2) * 64;
    const int wn0 = (warp & 3) * 32;

    if (MODE == 0) {
        if (tid < GROUPS) {
            s_mu[tid]  = g_gnmu[z * GROUPS + tid];
            s_inv[tid] = g_gninv[z * GROUPS + tid];
        }
        for (int i = tid; i < CCH; i += 256) {
            s_gam[i] = gamma[i];
            s_bet[i] = beta[i];
        }
        __syncthreads();
    }

    float cfr[4][4][4];
    #pragma unroll
    for (int i = 0; i < 4; i++)
        #pragma unroll
        for (int j = 0; j < 4; j++)
            #pragma unroll
            for (int q = 0; q < 4; q++) cfr[i][j][q] = 0.f;

    const int amr = tid >> 1;
    const int akw = (tid & 1) * 8;
    const int bkp = tid >> 5;
    const int bln = tid & 31;

    for (int kt = 0; kt < K; kt += BK) {
        {   // stage A: W[m][k] -> As[m][k/2]
            const float* ap = Wg + (size_t)(m0 + amr) * lda + kt + akw * 2;
            uint32_t buf[8];
            #pragma unroll
            for (int it = 0; it < 4; it++) {
                float4 v = *(const float4*)(ap + it * 4);
                buf[it * 2 + 0] = pack_bf2(v.x, v.y);
                buf[it * 2 + 1] = pack_bf2(v.z, v.w);
            }
            uint32_t* dst = As + amr * SW + akw;
            *(uint4*)(dst)     = *(uint4*)(buf);
            *(uint4*)(dst + 4) = *(uint4*)(buf + 4);
        }
        {   // stage B: X[k][n] -> Bs[n][k/2]  (+ GN for MODE 0)
            #pragma unroll
            for (int half = 0; half < 2; half++) {
                int kp = bkp + half * 8;
                int ch = kt + 2 * kp;
                const float* r0 = Xg + Boff + (size_t)ch * ldb + n0;
                const float* r1 = r0 + ldb;
                float a0 = 1.f, c0 = 0.f, a1 = 1.f, c1 = 0.f;
                if (MODE == 0) {
                    float i0 = s_inv[ch >> 4],       m0v = s_mu[ch >> 4];
                    float i1 = s_inv[(ch + 1) >> 4], m1v = s_mu[(ch + 1) >> 4];
                    a0 = i0 * s_gam[ch];     c0 = s_bet[ch]     - m0v * a0;
                    a1 = i1 * s_gam[ch + 1]; c1 = s_bet[ch + 1] - m1v * a1;
                }
                #pragma unroll
                for (int c = 0; c < 4; c++) {
                    int n = bln + 32 * c;
                    float v0 = r0[n], v1 = r1[n];
                    if (MODE == 0) { v0 = v0 * a0 + c0; v1 = v1 * a1 + c1; }
                    Bs[n * SW + kp] = pack_bf2(v0, v1);
                }
            }
        }
        __syncthreads();

        #pragma unroll
        for (int kk = 0; kk < 2; kk++) {
            const int wb = kk * 8;
            uint32_t af[4][4], bf[4][2];
            #pragma unroll
            for (int mi = 0; mi < 4; mi++) {
                const uint32_t* p = As + (wm0 + mi * 16 + g) * SW + wb + t;
                af[mi][0] = p[0];
                af[mi][1] = p[8 * SW];
                af[mi][2] = p[4];
                af[mi][3] = p[8 * SW + 4];
            }
            #pragma unroll
            for (int ni = 0; ni < 4; ni++) {
                const uint32_t* p = Bs + (wn0 + ni * 8 + g) * SW + wb + t;
                bf[ni][0] = p[0];
                bf[ni][1] = p[4];
            }
            #pragma unroll
            for (int mi = 0; mi < 4; mi++)
                #pragma unroll
                for (int ni = 0; ni < 4; ni++)
                    MMA_BF16(cfr[mi][ni], af[mi], bf[ni]);
        }
        __syncthreads();
    }

    #pragma unroll
    for (int mi = 0; mi < 4; mi++) {
        #pragma unroll
        for (int rr = 0; rr < 2; rr++) {
            int grow = m0 + wm0 + mi * 16 + g + rr * 8;
            float bv = bias[grow];
            if (MODE == 0) {
                int sect = grow >> 9;                 // 0=Q 1=K 2=V
                int ch   = grow & 511;
                float sc = (sect == 0) ? ATT_SCALE : 1.f;
                __nv_bfloat16* dst = (sect == 0) ? g_qc
                                   : (sect == 1) ? g_kc : g_vb;
                size_t base = ((size_t)z * CCH + ch) * NPIX;
                #pragma unroll
                for (int ni = 0; ni < 4; ni++) {
                    int gcol = n0 + wn0 + ni * 8 + 2 * t;
                    float v0 = (cfr[mi][ni][rr * 2 + 0] + bv) * sc;
                    float v1 = (cfr[mi][ni][rr * 2 + 1] + bv) * sc;
                    *(uint32_t*)(dst + base + gcol) = pack_bf2(v0, v1);
                }
            } else {
                #pragma unroll
                for (int ni = 0; ni < 4; ni++) {
                    int gcol = n0 + wn0 + ni * 8 + 2 * t;
                    size_t idx = (size_t)z * CCH * NPIX + (size_t)grow * N + gcol;
                    Cg[idx]     = cfr[mi][ni][rr * 2 + 0] + bv + res[idx];
                    Cg[idx + 1] = cfr[mi][ni][rr * 2 + 1] + bv + res[idx + 1];
                }
            }
        }
    }
}

// ---------------- prep: bf16 transpose Q,K to [bh][qk][c] --------------------
// grid (HD/32, NPIX/32, NBH*2), block (32,8). which = z&1 (0=Q, 1=K)
__global__ void prep_qkT() {
    __shared__ __nv_bfloat16 ts[32][33];
    const int z = blockIdx.z;
    const int bh = z >> 1, which = z & 1;
    const int b = bh >> 2, h = bh & 3;
    const int c0 = blockIdx.x * 32, q0 = blockIdx.y * 32;
    const __nv_bfloat16* src = (which == 0 ? g_qc : g_kc)
        + ((size_t)b * CCH + h * HD) * NPIX;
    __nv_bfloat16* dst = (which == 0 ? g_qT : g_kT) + (size_t)bh * NPIX * HD;

    #pragma unroll
    for (int i = 0; i < 4; i++) {
        int c = c0 + threadIdx.y + i * 8;
        ts[threadIdx.y + i * 8][threadIdx.x] = src[(size_t)c * NPIX + q0 + threadIdx.x];
    }
    __syncthreads();
    #pragma unroll
    for (int i = 0; i < 4; i++) {
        int q = q0 + threadIdx.y + i * 8;
        dst[(size_t)q * HD + c0 + threadIdx.x] = ts[threadIdx.x][threadIdx.y + i * 8];
    }
}

// ---------------- flash attention: plain-LDS bf16 mma (R7/R8-proven) ---------
#define LDW(p) (*(const uint32_t*)(p))
#define FSTR 136
#define TILE_B (128 * FSTR * 2)
#define QS_OFF  0
#define KS_OFF  (TILE_B)
#define VS_OFF  (2 * TILE_B)
#define PS_OFF  (3 * TILE_B)
#define RED_OFF (4 * TILE_B)
#define FLASH_SMEM (4 * TILE_B + 4096)

__global__ void __launch_bounds__(256, 1) flash_kernel() {
    extern __shared__ char smbuf[];
    __nv_bfloat16* Qs = (__nv_bfloat16*)(smbuf + QS_OFF);
    __nv_bfloat16* Ks = (__nv_bfloat16*)(smbuf + KS_OFF);
    __nv_bfloat16* Vs = (__nv_bfloat16*)(smbuf + VS_OFF);
    __nv_bfloat16* Ps = (__nv_bfloat16*)(smbuf + PS_OFF);
    float* redm = (float*)(smbuf + RED_OFF);
    float* redl = redm + 512;
    float* Ot   = (float*)(smbuf + KS_OFF);

    const int tid = threadIdx.x, lane = tid & 31, warp = tid >> 5;
    const int g = lane >> 2, t = lane & 3;
    const int wm = (warp >> 2) * 64, wn = (warp & 3) * 32;
    const int bh = blockIdx.y, b = bh >> 2, h = bh & 3;
    const int q0 = blockIdx.x * 128;

    const __nv_bfloat16* qsrc = g_qT + (size_t)bh * NPIX * HD + (size_t)q0 * HD;
    const __nv_bfloat16* ksrc = g_kT + (size_t)bh * NPIX * HD;
    const __nv_bfloat16* vsrc = g_vb + ((size_t)b * CCH + h * HD) * NPIX;

    #pragma unroll
    for (int it = 0; it < 8; it++) {
        int idx = tid + it * 256;
        int row = idx >> 4, col8 = (idx & 15) * 8;
        *(uint4*)(Qs + row * FSTR + col8) = *(const uint4*)(qsrc + row * HD + col8);
    }

    float oacc[4][4][4];
    #pragma unroll
    for (int a = 0; a < 4; a++)
        #pragma unroll
        for (int c = 0; c < 4; c++)
            #pragma unroll
            for (int q = 0; q < 4; q++) oacc[a][c][q] = 0.f;
    float m_run[4][2], l_run[4][2];
    #pragma unroll
    for (int a = 0; a < 4; a++) { m_run[a][0] = m_run[a][1] = -1e30f;
                                  l_run[a][0] = l_run[a][1] = 0.f; }

    for (int kc = 0; kc < 8; kc++) {
        #pragma unroll
        for (int it = 0; it < 8; it++) {
            int idx = tid + it * 256;
            int row = idx >> 4, col8 = (idx & 15) * 8;
            *(uint4*)(Ks + row * FSTR + col8) =
                *(const uint4*)(ksrc + (size_t)(kc * 128 + row) * HD + col8);
            *(uint4*)(Vs + row * FSTR + col8) =
                *(const uint4*)(vsrc + (size_t)row * NPIX + kc * 128 + col8);
        }
        __syncthreads();

        float sacc[4][4][4];
        #pragma unroll
        for (int a = 0; a < 4; a++)
            #pragma unroll
            for (int c = 0; c < 4; c++)
                #pragma unroll
                for (int q = 0; q < 4; q++) sacc[a][c][q] = 0.f;
        #pragma unroll
        for (int ks = 0; ks < 8; ks++) {
            const int kb = ks * 16;
            uint32_t af[4][4], bf[4][2];
            #pragma unroll
            for (int mi = 0; mi < 4; mi++) {
                const __nv_bfloat16* p = Qs + (wm + mi * 16 + g) * FSTR + kb + 2 * t;
                af[mi][0] = LDW(p);
                af[mi][1] = LDW(p + 8 * FSTR);
                af[mi][2] = LDW(p + 8);
                af[mi][3] = LDW(p + 8 * FSTR + 8);
            }
            #pragma unroll
            for (int ni = 0; ni < 4; ni++) {
                const __nv_bfloat16* p = Ks + (wn + ni * 8 + g) * FSTR + kb + 2 * t;
                bf[ni][0] = LDW(p);
                bf[ni][1] = LDW(p + 8);
            }
            #pragma unroll
            for (int mi = 0; mi < 4; mi++)
                #pragma unroll
                for (int ni = 0; ni < 4; ni++)
                    MMA_BF16(sacc[mi][ni], af[mi], bf[ni]);
        }

        #pragma unroll
        for (int mi = 0; mi < 4; mi++)
            #pragma unroll
            for (int rr = 0; rr < 2; rr++) {
                float mx = -1e30f;
                #pragma unroll
                for (int ni = 0; ni < 4; ni++)
                    mx = fmaxf(mx, fmaxf(sacc[mi][ni][2 * rr], sacc[mi][ni][2 * rr + 1]));
                mx = fmaxf(mx, __shfl_xor_sync(0xffffffffu, mx, 1));
                mx = fmaxf(mx, __shfl_xor_sync(0xffffffffu, mx, 2));
                if (t == 0) redm[(warp & 3) * 128 + wm + mi * 16 + g + 8 * rr] = mx;
            }
        __syncthreads();

        float mnew[4][2], al[4][2];
        #pragma unroll
        for (int mi = 0; mi < 4; mi++)
            #pragma unroll
            for (int rr = 0; rr < 2; rr++) {
                int r = wm + mi * 16 + g + 8 * rr;
                float mx = fmaxf(fmaxf(redm[r], redm[128 + r]),
                                 fmaxf(redm[256 + r], redm[384 + r]));
                float mn = fmaxf(m_run[mi][rr], mx);
                al[mi][rr]   = __expf(m_run[mi][rr] - mn);
                mnew[mi][rr] = mn;
            }

        float lloc[4][2] = {};
        #pragma unroll
        for (int mi = 0; mi < 4; mi++)
            #pragma unroll
            for (int ni = 0; ni < 4; ni++)
                #pragma unroll
                for (int rr = 0; rr < 2; rr++) {
                    float p0 = __expf(sacc[mi][ni][2 * rr]     - mnew[mi][rr]);
                    float p1 = __expf(sacc[mi][ni][2 * rr + 1] - mnew[mi][rr]);
                    lloc[mi][rr] += p0 + p1;
                    *(uint32_t*)(Ps + (wm + mi * 16 + g + 8 * rr) * FSTR
                                    + wn + ni * 8 + 2 * t) = pack_bf2(p0, p1);
                }
        #pragma unroll
        for (int mi = 0; mi < 4; mi++)
            #pragma unroll
            for (int rr = 0; rr < 2; rr++) {
                float s = lloc[mi][rr];
                s += __shfl_xor_sync(0xffffffffu, s, 1);
                s += __shfl_xor_sync(0xffffffffu, s, 2);
                if (t == 0) redl[(warp & 3) * 128 + wm + mi * 16 + g + 8 * rr] = s;
            }
        __syncthreads();

        #pragma unroll
        for (int mi = 0; mi < 4; mi++)
            #pragma unroll
            for (int rr = 0; rr < 2; rr++) {
                int r = wm + mi * 16 + g + 8 * rr;
                float cl = redl[r] + redl[128 + r] + redl[256 + r] + redl[384 + r];
                l_run[mi][rr] = l_run[mi][rr] * al[mi][rr] + cl;
                m_run[mi][rr] = mnew[mi][rr];
            }
        #pragma unroll
        for (int mi = 0; mi < 4; mi++)
            #pragma unroll
            for (int ni = 0; ni < 4; ni++)
                #pragma unroll
                for (int q = 0; q < 4; q++)
                    oacc[mi][ni][q] *= al[mi][q >> 1];

        #pragma unroll
        for (int ks = 0; ks < 8; ks++) {
            const int kb = ks * 16;
            uint32_t pf[4][4], vf[4][2];
            #pragma unroll
            for (int mi = 0; mi < 4; mi++) {
                const __nv_bfloat16* p = Ps + (wm + mi * 16 + g) * FSTR + kb + 2 * t;
                pf[mi][0] = LDW(p);
                pf[mi][1] = LDW(p + 8 * FSTR);
                pf[mi][2] = LDW(p + 8);
                pf[mi][3] = LDW(p + 8 * FSTR + 8);
            }
            #pragma unroll
            for (int ni = 0; ni < 4; ni++) {
                const __nv_bfloat16* p = Vs + (wn + ni * 8 + g) * FSTR + kb + 2 * t;
                vf[ni][0] = LDW(p);
                vf[ni][1] = LDW(p + 8);
            }
            #pragma unroll
            for (int mi = 0; mi < 4; mi++)
                #pragma unroll
                for (int ni = 0; ni < 4; ni++)
                    MMA_BF16(oacc[mi][ni], pf[mi], vf[ni]);
        }
        __syncthreads();
    }

    float inv[4][2];
    #pragma unroll
    for (int mi = 0; mi < 4; mi++) {
        inv[mi][0] = 1.f / l_run[mi][0];
        inv[mi][1] = 1.f / l_run[mi][1];
    }
    #pragma unroll
    for (int mi = 0; mi < 4; mi++)
        #pragma unroll
        for (int ni = 0; ni < 4; ni++)
            #pragma unroll
            for (int q = 0; q < 4; q++) {
                int col = wn + ni * 8 + 2 * t + (q & 1);
                int row = wm + mi * 16 + g + 8 * (q >> 1);
                Ot[col * 132 + row] = oacc[mi][ni][q] * inv[mi][q >> 1];
            }
    __syncthreads();
    float* og = g_att + ((size_t)b * CCH + h * HD) * NPIX + q0;
    #pragma unroll
    for (int it = 0; it < 16; it++) {
        int idx = tid + it * 256;
        int c = idx >> 5, q4 = (idx & 31) << 2;
        *(float4*)(og + (size_t)c * NPIX + q4) = *(const float4*)(Ot + c * 132 + q4);
    }
}

// ---------------- launch -----------------------------------------------------
extern "C" void kernel_launch(void* const* d_in, const int* in_sizes, int n_in,
                              void* d_out, int out_size) {
    const float* x      = (const float*)d_in[0];
    const float* gamma  = (const float*)d_in[1];
    const float* beta   = (const float*)d_in[2];
    const float* w_qkv  = (const float*)d_in[3];
    const float* b_qkv  = (const float*)d_in[4];
    const float* w_proj = (const float*)d_in[5];
    const float* b_proj = (const float*)d_in[6];
    float* out = (float*)d_out;

    float* att;
    cudaGetSymbolAddress((void**)&att, g_att);

    cudaFuncSetAttribute(flash_kernel,
        cudaFuncAttributeMaxDynamicSharedMemorySize, FLASH_SMEM);

    // 1) GroupNorm statistics
    gn_stats<<<BATCH * GROUPS, 256>>>(x);

    // 2) QKV projection (bf16, GN fused in, bf16 Q/K/V out)
    bf16_gemm<0><<<dim3(NPIX / BN, 3 * CCH / BM, BATCH), 256>>>(
        w_qkv, x, nullptr, b_qkv, nullptr, gamma, beta,
        3 * CCH, NPIX, CCH, CCH, NPIX);

    // 3) prep: Q/K bf16 transpose to [bh][q/key][c]
    prep_qkT<<<dim3(HD / 32, NPIX / 32, NBH * 2), dim3(32, 8)>>>();

    // 4) fused flash attention (bf16)
    flash_kernel<<<dim3(NPIX / 128, NBH), 256, FLASH_SMEM>>>();

    // 5) proj + bias + residual (bf16)
    bf16_gemm<3><<<dim3(NPIX / BN, CCH / BM, BATCH), 256>>>(
        w_proj, att, out, b_proj, x, nullptr, nullptr,
        CCH, NPIX, CCH, CCH, NPIX);
}

// round 13
// speedup vs baseline: 4.6617x; 1.0453x over previous
#include <cuda_runtime.h>
#include <cuda_bf16.h>
#include <cstdint>

#define BATCH   16
#define CCH     512
#define NPIX    1024          // 32*32
#define HEADS   4
#define HD      128           // CCH / HEADS
#define GROUPS  32
#define CPG     (CCH / GROUPS)   // 16
#define GEPS    1e-5f
#define ATT_SCALE 0.088388347648318447f   // 128^-0.5
#define NBH     (BATCH * HEADS)           // 64

// ---------------- scratch (device globals; no allocations allowed) ----------
__device__ float g_att[BATCH * CCH * NPIX];                 // 33.5 MB fp32
__device__ float g_gnmu [BATCH * GROUPS];
__device__ float g_gninv[BATCH * GROUPS];
__device__ __nv_bfloat16 g_qc[(size_t)BATCH * CCH * NPIX];  // [b][c][q], scaled
__device__ __nv_bfloat16 g_kc[(size_t)BATCH * CCH * NPIX];  // [b][c][q]
__device__ __nv_bfloat16 g_vb[(size_t)BATCH * CCH * NPIX];  // [b][c][key]
__device__ __nv_bfloat16 g_qT[(size_t)NBH * NPIX * HD];     // [bh][q][c]
__device__ __nv_bfloat16 g_kT[(size_t)NBH * NPIX * HD];     // [bh][key][c]

__device__ __forceinline__ uint32_t pack_bf2(float a, float b) {
    __nv_bfloat162 h = __floats2bfloat162_rn(a, b);
    return *(uint32_t*)&h;
}

// ---------------- GroupNorm stats only ---------------------------------------
__global__ void gn_stats(const float* __restrict__ x) {
    const int bg = blockIdx.x;
    const int b  = bg / GROUPS;
    const int g  = bg % GROUPS;
    const int M  = CPG * NPIX;                  // 16384
    const float* xp = x + ((size_t)b * CCH + (size_t)g * CPG) * NPIX;

    float s = 0.f, ss = 0.f;
    for (int i = threadIdx.x; i < M; i += blockDim.x) {
        float v = xp[i];
        s += v; ss += v * v;
    }
    __shared__ float red[64];
    #pragma unroll
    for (int o = 16; o; o >>= 1) {
        s  += __shfl_xor_sync(0xffffffffu, s,  o);
        ss += __shfl_xor_sync(0xffffffffu, ss, o);
    }
    const int warp = threadIdx.x >> 5, lane = threadIdx.x & 31;
    if (lane == 0) { red[warp] = s; red[warp + 32] = ss; }
    __syncthreads();
    if (threadIdx.x == 0) {
        float s2 = 0.f, ss2 = 0.f;
        #pragma unroll
        for (int i = 0; i < 8; i++) { s2 += red[i]; ss2 += red[i + 32]; }
        float mu  = s2 / (float)M;
        float var = ss2 / (float)M - mu * mu;
        g_gnmu[bg]  = mu;
        g_gninv[bg] = rsqrtf(var + GEPS);
    }
}

// ---------------- bf16 MMA GEMM (R8/R9-proven) --------------------------------
#define BM 128
#define BN 128
#define BK 32
#define SW 20

#define MMA_BF16(c, a, b) \
    asm volatile("mma.sync.aligned.m16n8k16.row.col.f32.bf16.bf16.f32 " \
        "{%0,%1,%2,%3},{%4,%5,%6,%7},{%8,%9},{%0,%1,%2,%3};" \
        : "+f"((c)[0]), "+f"((c)[1]), "+f"((c)[2]), "+f"((c)[3]) \
        : "r"((a)[0]), "r"((a)[1]), "r"((a)[2]), "r"((a)[3]), \
          "r"((b)[0]), "r"((b)[1]))

template<int MODE>
__global__ void __launch_bounds__(256, 2)
bf16_gemm(const float* __restrict__ Wg, const float* __restrict__ Xg,
          float* __restrict__ Cg,
          const float* __restrict__ bias, const float* __restrict__ res,
          const float* __restrict__ gamma, const float* __restrict__ beta,
          int M, int N, int K, int lda, int ldb) {
    const int z  = blockIdx.z;
    const int m0 = blockIdx.y * BM;
    const int n0 = blockIdx.x * BN;
    const size_t Boff = (size_t)z * CCH * NPIX;

    __shared__ uint32_t As[BM * SW];
    __shared__ uint32_t Bs[BN * SW];
    __shared__ float s_mu[GROUPS], s_inv[GROUPS];
    __shared__ float s_gam[CCH], s_bet[CCH];

    const int tid  = threadIdx.x;
    const int lane = tid & 31;
    const int warp = tid >> 5;
    const int g = lane >> 2, t = lane & 3;
    const int wm0 = (warp >> 2) * 64;
    const int wn0 = (warp & 3) * 32;

    if (MODE == 0) {
        if (tid < GROUPS) {
            s_mu[tid]  = g_gnmu[z * GROUPS + tid];
            s_inv[tid] = g_gninv[z * GROUPS + tid];
        }
        for (int i = tid; i < CCH; i += 256) {
            s_gam[i] = gamma[i];
            s_bet[i] = beta[i];
        }
        __syncthreads();
    }

    float cfr[4][4][4];
    #pragma unroll
    for (int i = 0; i < 4; i++)
        #pragma unroll
        for (int j = 0; j < 4; j++)
            #pragma unroll
            for (int q = 0; q < 4; q++) cfr[i][j][q] = 0.f;

    const int amr = tid >> 1;
    const int akw = (tid & 1) * 8;
    const int bkp = tid >> 5;
    const int bln = tid & 31;

    for (int kt = 0; kt < K; kt += BK) {
        {   // stage A: W[m][k] -> As[m][k/2]
            const float* ap = Wg + (size_t)(m0 + amr) * lda + kt + akw * 2;
            uint32_t buf[8];
            #pragma unroll
            for (int it = 0; it < 4; it++) {
                float4 v = *(const float4*)(ap + it * 4);
                buf[it * 2 + 0] = pack_bf2(v.x, v.y);
                buf[it * 2 + 1] = pack_bf2(v.z, v.w);
            }
            uint32_t* dst = As + amr * SW + akw;
            *(uint4*)(dst)     = *(uint4*)(buf);
            *(uint4*)(dst + 4) = *(uint4*)(buf + 4);
        }
        {   // stage B: X[k][n] -> Bs[n][k/2]  (+ GN for MODE 0)
            #pragma unroll
            for (int half = 0; half < 2; half++) {
                int kp = bkp + half * 8;
                int ch = kt + 2 * kp;
                const float* r0 = Xg + Boff + (size_t)ch * ldb + n0;
                const float* r1 = r0 + ldb;
                float a0 = 1.f, c0 = 0.f, a1 = 1.f, c1 = 0.f;
                if (MODE == 0) {
                    float i0 = s_inv[ch >> 4],       m0v = s_mu[ch >> 4];
                    float i1 = s_inv[(ch + 1) >> 4], m1v = s_mu[(ch + 1) >> 4];
                    a0 = i0 * s_gam[ch];     c0 = s_bet[ch]     - m0v * a0;
                    a1 = i1 * s_gam[ch + 1]; c1 = s_bet[ch + 1] - m1v * a1;
                }
                #pragma unroll
                for (int c = 0; c < 4; c++) {
                    int n = bln + 32 * c;
                    float v0 = r0[n], v1 = r1[n];
                    if (MODE == 0) { v0 = v0 * a0 + c0; v1 = v1 * a1 + c1; }
                    Bs[n * SW + kp] = pack_bf2(v0, v1);
                }
            }
        }
        __syncthreads();

        #pragma unroll
        for (int kk = 0; kk < 2; kk++) {
            const int wb = kk * 8;
            uint32_t af[4][4], bf[4][2];
            #pragma unroll
            for (int mi = 0; mi < 4; mi++) {
                const uint32_t* p = As + (wm0 + mi * 16 + g) * SW + wb + t;
                af[mi][0] = p[0];
                af[mi][1] = p[8 * SW];
                af[mi][2] = p[4];
                af[mi][3] = p[8 * SW + 4];
            }
            #pragma unroll
            for (int ni = 0; ni < 4; ni++) {
                const uint32_t* p = Bs + (wn0 + ni * 8 + g) * SW + wb + t;
                bf[ni][0] = p[0];
                bf[ni][1] = p[4];
            }
            #pragma unroll
            for (int mi = 0; mi < 4; mi++)
                #pragma unroll
                for (int ni = 0; ni < 4; ni++)
                    MMA_BF16(cfr[mi][ni], af[mi], bf[ni]);
        }
        __syncthreads();
    }

    #pragma unroll
    for (int mi = 0; mi < 4; mi++) {
        #pragma unroll
        for (int rr = 0; rr < 2; rr++) {
            int grow = m0 + wm0 + mi * 16 + g + rr * 8;
            float bv = bias[grow];
            if (MODE == 0) {
                int sect = grow >> 9;                 // 0=Q 1=K 2=V
                int ch   = grow & 511;
                float sc = (sect == 0) ? ATT_SCALE : 1.f;
                __nv_bfloat16* dst = (sect == 0) ? g_qc
                                   : (sect == 1) ? g_kc : g_vb;
                size_t base = ((size_t)z * CCH + ch) * NPIX;
                #pragma unroll
                for (int ni = 0; ni < 4; ni++) {
                    int gcol = n0 + wn0 + ni * 8 + 2 * t;
                    float v0 = (cfr[mi][ni][rr * 2 + 0] + bv) * sc;
                    float v1 = (cfr[mi][ni][rr * 2 + 1] + bv) * sc;
                    *(uint32_t*)(dst + base + gcol) = pack_bf2(v0, v1);
                }
            } else {
                #pragma unroll
                for (int ni = 0; ni < 4; ni++) {
                    int gcol = n0 + wn0 + ni * 8 + 2 * t;
                    size_t idx = (size_t)z * CCH * NPIX + (size_t)grow * N + gcol;
                    Cg[idx]     = cfr[mi][ni][rr * 2 + 0] + bv + res[idx];
                    Cg[idx + 1] = cfr[mi][ni][rr * 2 + 1] + bv + res[idx + 1];
                }
            }
        }
    }
}

// ---------------- prep: bf16 transpose Q,K to [bh][qk][c] --------------------
__global__ void prep_qkT() {
    __shared__ __nv_bfloat16 ts[32][33];
    const int z = blockIdx.z;
    const int bh = z >> 1, which = z & 1;
    const int b = bh >> 2, h = bh & 3;
    const int c0 = blockIdx.x * 32, q0 = blockIdx.y * 32;
    const __nv_bfloat16* src = (which == 0 ? g_qc : g_kc)
        + ((size_t)b * CCH + h * HD) * NPIX;
    __nv_bfloat16* dst = (which == 0 ? g_qT : g_kT) + (size_t)bh * NPIX * HD;

    #pragma unroll
    for (int i = 0; i < 4; i++) {
        int c = c0 + threadIdx.y + i * 8;
        ts[threadIdx.y + i * 8][threadIdx.x] = src[(size_t)c * NPIX + q0 + threadIdx.x];
    }
    __syncthreads();
    #pragma unroll
    for (int i = 0; i < 4; i++) {
        int q = q0 + threadIdx.y + i * 8;
        dst[(size_t)q * HD + c0 + threadIdx.x] = ts[threadIdx.x][threadIdx.y + i * 8];
    }
}

// ---------------- flash attention: FA2 layout, R9-proven staging ------------
#define LDW(p) (*(const uint32_t*)(p))
#define FSTR 136
#define TILE_B (128 * FSTR * 2)        // 34816 bytes
#define QS_OFF  0
#define K_OFF   (TILE_B)
#define V_OFF   (2 * TILE_B)
#define FLASH_SMEM (3 * TILE_B + 128)

__global__ void __launch_bounds__(256, 1) flash_kernel() {
    extern __shared__ char smbuf[];
    __nv_bfloat16* Qs = (__nv_bfloat16*)(smbuf + QS_OFF);
    __nv_bfloat16* Ks = (__nv_bfloat16*)(smbuf + K_OFF);
    __nv_bfloat16* Vs = (__nv_bfloat16*)(smbuf + V_OFF);
    float* Ot = (float*)(smbuf + K_OFF);   // reused after mainloop

    const int tid = threadIdx.x, lane = tid & 31, warp = tid >> 5;
    const int g = lane >> 2, t = lane & 3;
    const int wm = warp * 16;               // 16 query rows per warp
    const int bh = blockIdx.y, b = bh >> 2, h = bh & 3;
    const int q0 = blockIdx.x * 128;

    const __nv_bfloat16* qsrc = g_qT + (size_t)bh * NPIX * HD + (size_t)q0 * HD;
    const __nv_bfloat16* ksrc = g_kT + (size_t)bh * NPIX * HD;
    const __nv_bfloat16* vsrc = g_vb + ((size_t)b * CCH + h * HD) * NPIX;

    // stage Q (R9-proven geometry): Qs[q][c]
    #pragma unroll
    for (int it = 0; it < 8; it++) {
        int idx = tid + it * 256;
        int row = idx >> 4, col8 = (idx & 15) * 8;
        *(uint4*)(Qs + row * FSTR + col8) = *(const uint4*)(qsrc + row * HD + col8);
    }

    float oacc[16][4];
    #pragma unroll
    for (int nj = 0; nj < 16; nj++)
        #pragma unroll
        for (int q = 0; q < 4; q++) oacc[nj][q] = 0.f;
    float m_run[2] = { -1e30f, -1e30f }, l_run[2] = { 0.f, 0.f };

    for (int kc = 0; kc < 8; kc++) {
        __syncthreads();                   // prior chunk's Vs reads done
        // stage K/V chunk (R9-proven geometry): full 128x128 coverage
        #pragma unroll
        for (int it = 0; it < 8; it++) {
            int idx = tid + it * 256;
            int row = idx >> 4, col8 = (idx & 15) * 8;
            *(uint4*)(Ks + row * FSTR + col8) =
                *(const uint4*)(ksrc + (size_t)(kc * 128 + row) * HD + col8);
            *(uint4*)(Vs + row * FSTR + col8) =
                *(const uint4*)(vsrc + (size_t)row * NPIX + kc * 128 + col8);
        }
        __syncthreads();                   // staged data visible

        // ---- S = Q K^T : warp rows wm..wm+15, all 128 keys ----
        float sacc[16][4];
        #pragma unroll
        for (int ni = 0; ni < 16; ni++)
            #pragma unroll
            for (int q = 0; q < 4; q++) sacc[ni][q] = 0.f;
        #pragma unroll
        for (int ks = 0; ks < 8; ks++) {
            const int kb = ks * 16;
            uint32_t af[4];
            const __nv_bfloat16* pq = Qs + (wm + g) * FSTR + kb + 2 * t;
            af[0] = LDW(pq);
            af[1] = LDW(pq + 8 * FSTR);
            af[2] = LDW(pq + 8);
            af[3] = LDW(pq + 8 * FSTR + 8);
            #pragma unroll
            for (int ni = 0; ni < 16; ni++) {
                uint32_t bf[2];
                const __nv_bfloat16* pk = Ks + (ni * 8 + g) * FSTR + kb + 2 * t;
                bf[0] = LDW(pk);
                bf[1] = LDW(pk + 8);
                MMA_BF16(sacc[ni], af, bf);
            }
        }

        // ---- online softmax: warp-local (shfl over t lanes only) ----
        float mnew[2], al[2];
        #pragma unroll
        for (int rr = 0; rr < 2; rr++) {
            float mx = -1e30f;
            #pragma unroll
            for (int ni = 0; ni < 16; ni++)
                mx = fmaxf(mx, fmaxf(sacc[ni][2 * rr], sacc[ni][2 * rr + 1]));
            mx = fmaxf(mx, __shfl_xor_sync(0xffffffffu, mx, 1));
            mx = fmaxf(mx, __shfl_xor_sync(0xffffffffu, mx, 2));
            float mn = fmaxf(m_run[rr], mx);
            al[rr] = __expf(m_run[rr] - mn);
            mnew[rr] = mn;
        }
        uint32_t pp[16][2];
        float lloc[2] = { 0.f, 0.f };
        #pragma unroll
        for (int ni = 0; ni < 16; ni++) {
            float p0 = __expf(sacc[ni][0] - mnew[0]);
            float p1 = __expf(sacc[ni][1] - mnew[0]);
            float p2 = __expf(sacc[ni][2] - mnew[1]);
            float p3 = __expf(sacc[ni][3] - mnew[1]);
            lloc[0] += p0 + p1;
            lloc[1] += p2 + p3;
            pp[ni][0] = pack_bf2(p0, p1);
            pp[ni][1] = pack_bf2(p2, p3);
        }
        #pragma unroll
        for (int rr = 0; rr < 2; rr++) {
            float s = lloc[rr];
            s += __shfl_xor_sync(0xffffffffu, s, 1);
            s += __shfl_xor_sync(0xffffffffu, s, 2);
            l_run[rr] = l_run[rr] * al[rr] + s;
            m_run[rr] = mnew[rr];
        }
        #pragma unroll
        for (int nj = 0; nj < 16; nj++) {
            oacc[nj][0] *= al[0]; oacc[nj][1] *= al[0];
            oacc[nj][2] *= al[1]; oacc[nj][3] *= al[1];
        }

        // ---- O += P V^T : P in registers (A-frag = pp), B from Vs ----
        #pragma unroll
        for (int ks = 0; ks < 8; ks++) {
            uint32_t af[4] = { pp[2 * ks][0], pp[2 * ks][1],
                               pp[2 * ks + 1][0], pp[2 * ks + 1][1] };
            const int kb = ks * 16;
            #pragma unroll
            for (int nj = 0; nj < 16; nj++) {
                uint32_t bf[2];
                const __nv_bfloat16* pv = Vs + (nj * 8 + g) * FSTR + kb + 2 * t;
                bf[0] = LDW(pv);
                bf[1] = LDW(pv + 8);
                MMA_BF16(oacc[nj], af, bf);
            }
        }
    }

    // ---- epilogue: smem transpose -> coalesced [c][q] store ----
    __syncthreads();                       // before reusing K/V smem as Ot
    float inv0 = 1.f / l_run[0], inv1 = 1.f / l_run[1];
    #pragma unroll
    for (int nj = 0; nj < 16; nj++)
        #pragma unroll
        for (int q = 0; q < 4; q++) {
            int col = nj * 8 + 2 * t + (q & 1);              // c
            int row = wm + g + 8 * (q >> 1);                 // q
            Ot[col * 132 + row] = oacc[nj][q] * ((q >> 1) ? inv1 : inv0);
        }
    __syncthreads();
    float* og = g_att + ((size_t)b * CCH + h * HD) * NPIX + q0;
    #pragma unroll
    for (int it = 0; it < 16; it++) {
        int idx = tid + it * 256;
        int c = idx >> 5, q4 = (idx & 31) << 2;
        *(float4*)(og + (size_t)c * NPIX + q4) = *(const float4*)(Ot + c * 132 + q4);
    }
}

// ---------------- launch -----------------------------------------------------
extern "C" void kernel_launch(void* const* d_in, const int* in_sizes, int n_in,
                              void* d_out, int out_size) {
    const float* x      = (const float*)d_in[0];
    const float* gamma  = (const float*)d_in[1];
    const float* beta   = (const float*)d_in[2];
    const float* w_qkv  = (const float*)d_in[3];
    const float* b_qkv  = (const float*)d_in[4];
    const float* w_proj = (const float*)d_in[5];
    const float* b_proj = (const float*)d_in[6];
    float* out = (float*)d_out;

    float* att;
    cudaGetSymbolAddress((void**)&att, g_att);

    cudaFuncSetAttribute(flash_kernel,
        cudaFuncAttributeMaxDynamicSharedMemorySize, FLASH_SMEM);

    // 1) GroupNorm statistics
    gn_stats<<<BATCH * GROUPS, 256>>>(x);

    // 2) QKV projection (bf16, GN fused in, bf16 Q/K/V out)
    bf16_gemm<0><<<dim3(NPIX / BN, 3 * CCH / BM, BATCH), 256>>>(
        w_qkv, x, nullptr, b_qkv, nullptr, gamma, beta,
        3 * CCH, NPIX, CCH, CCH, NPIX);

    // 3) prep: Q/K bf16 transpose to [bh][q/key][c]
    prep_qkT<<<dim3(HD / 32, NPIX / 32, NBH * 2), dim3(32, 8)>>>();

    // 4) fused flash attention (bf16, FA2 layout, register P)
    flash_kernel<<<dim3(NPIX / 128, NBH), 256, FLASH_SMEM>>>();

    // 5) proj + bias + residual (bf16)
    bf16_gemm<3><<<dim3(NPIX / BN, CCH / BM, BATCH), 256>>>(
        w_proj, att, out, b_proj, x, nullptr, nullptr,
        CCH, NPIX, CCH, CCH, NPIX);
}